// round 5
// baseline (speedup 1.0000x reference)
#include <cuda_runtime.h>

#define NEG_SLOPE 0.2f
#define BN_EPS_F  1e-5f
#define FULLM 0xffffffffu

static constexpr int NMAX = 100000;
static constexpr int EMAX = 1700000;

// ---------------- scratch (static device globals; no allocation) ----------------
__device__ float  g_h1  [(size_t)NMAX * 128];
__device__ float  g_agg1[(size_t)NMAX * 128];
__device__ float  g_h2  [(size_t)NMAX * 80];
__device__ float2 g_as1 [NMAX];
__device__ float2 g_ad1 [NMAX];
__device__ float2 g_as2 [NMAX];
__device__ float2 g_ad2 [NMAX];
__device__ int    g_deg   [NMAX];
__device__ int    g_incl  [NMAX];
__device__ int    g_rowptr[NMAX + 1];
__device__ int    g_cursor[NMAX];
__device__ int    g_col   [EMAX];
__device__ int    g_bsum  [256];
__device__ float  g_colsum[128];
__device__ float  g_colsq [128];
__device__ float  g_scale [128];
__device__ float  g_shift [128];

// ---------------- CSR build ----------------
__global__ void zero_init_k(int* deg, float* colsum, float* colsq, int n) {
    int i = blockIdx.x * blockDim.x + threadIdx.x;
    if (i < n) deg[i] = 0;
    if (i < 128) { colsum[i] = 0.f; colsq[i] = 0.f; }
}

__global__ void hist_k(const int* __restrict__ dst, int* __restrict__ deg, int E) {
    int e = blockIdx.x * blockDim.x + threadIdx.x;
    if (e < E) atomicAdd(&deg[dst[e]], 1);
}

// per-block (1024) inclusive scan + block sums
__global__ void scan1_k(const int* __restrict__ deg, int* __restrict__ incl,
                        int* __restrict__ bsum, int n) {
    __shared__ int wsum[32];
    const int tid = threadIdx.x;
    const int gid = blockIdx.x * 1024 + tid;
    const int lane = tid & 31, w = tid >> 5;
    int x = (gid < n) ? deg[gid] : 0;
    #pragma unroll
    for (int o = 1; o < 32; o <<= 1) {
        int t = __shfl_up_sync(FULLM, x, o);
        if (lane >= o) x += t;
    }
    if (lane == 31) wsum[w] = x;
    __syncthreads();
    if (w == 0) {
        int y = wsum[lane];
        #pragma unroll
        for (int o = 1; o < 32; o <<= 1) {
            int t = __shfl_up_sync(FULLM, y, o);
            if (lane >= o) y += t;
        }
        wsum[lane] = y;
    }
    __syncthreads();
    if (w > 0) x += wsum[w - 1];
    if (gid < n) incl[gid] = x;
    if (tid == 1023) bsum[blockIdx.x] = x;
}

// parallel exclusive scan of <=128 block sums (one block, 128 threads)
__global__ void scan2_k(int* bsum, int nb) {
    __shared__ int ws[4];
    const int tid = threadIdx.x, lane = tid & 31, w = tid >> 5;
    int orig = (tid < nb) ? bsum[tid] : 0;
    int x = orig;
    #pragma unroll
    for (int o = 1; o < 32; o <<= 1) {
        int t = __shfl_up_sync(FULLM, x, o);
        if (lane >= o) x += t;
    }
    if (lane == 31) ws[w] = x;
    __syncthreads();
    int add = 0;
    #pragma unroll
    for (int k = 0; k < 4; k++) if (k < w) add += ws[k];
    if (tid < nb) bsum[tid] = x + add - orig;   // exclusive
}

// rowptr (exclusive, length n+1) + cursor
__global__ void scan3_k(const int* __restrict__ incl, const int* __restrict__ bsum,
                        const int* __restrict__ deg, int* __restrict__ rowptr,
                        int* __restrict__ cursor, int n) {
    int i = blockIdx.x * blockDim.x + threadIdx.x;
    if (i < n) {
        int v = incl[i] + bsum[i >> 10];
        rowptr[i + 1] = v;
        cursor[i] = v - deg[i];
    }
    if (i == 0) rowptr[0] = 0;
}

__global__ void fill_k(const int* __restrict__ src, const int* __restrict__ dst,
                       int* __restrict__ cursor, int* __restrict__ col, int E) {
    int e = blockIdx.x * blockDim.x + threadIdx.x;
    if (e < E) {
        int p = atomicAdd(&cursor[dst[e]], 1);
        col[p] = src[e];
    }
}

// ---- GEMM: H[n,NOUT] = X[n,128] @ W[128,NOUT], optional BN fold on X,
//      fused epilogue: AS/AD attention dot-products. A tile stored transposed. ----
template<int NOUT>
__global__ __launch_bounds__(256, 2)
void gemm_k(const float* __restrict__ X, const float* __restrict__ W,
            float* __restrict__ H, int n,
            const float* __restrict__ scale, const float* __restrict__ shift,
            const float* __restrict__ attS, const float* __restrict__ attD,
            float2* __restrict__ AS, float2* __restrict__ AD)
{
    constexpr int TN = NOUT / 16;            // 8 for 128, 5 for 80
    extern __shared__ float smem[];
    float* sW  = smem;                       // [128 * NOUT]
    float* sXT = smem + 128 * NOUT;          // [128 * 68] transposed: sXT[k*68 + r]

    const int tid = threadIdx.x;
    const int tx  = tid & 15;
    const int ty  = tid >> 4;
    const int row0 = blockIdx.x * 64;

    for (int i = tid; i < 128 * NOUT; i += 256) sW[i] = W[i];
    const bool bn = (scale != nullptr);
    for (int i = tid; i < 64 * 128; i += 256) {
        int r = i >> 7, c = i & 127;
        int gr = row0 + r;
        float v = (gr < n) ? X[(size_t)gr * 128 + c] : 0.0f;
        if (bn) v = fmaf(v, scale[c], shift[c]);
        sXT[c * 68 + r] = v;
    }
    __syncthreads();

    float acc[4][TN];
    #pragma unroll
    for (int i = 0; i < 4; i++)
        #pragma unroll
        for (int j = 0; j < TN; j++) acc[i][j] = 0.0f;

    #pragma unroll 8
    for (int k = 0; k < 128; k++) {
        float4 a4 = *reinterpret_cast<const float4*>(sXT + k * 68 + ty * 4);
        float a[4] = {a4.x, a4.y, a4.z, a4.w};
        float b[TN];
        if constexpr (TN == 8) {
            const float4* bp = reinterpret_cast<const float4*>(sW + k * NOUT + tx * 8);
            float4 b0 = bp[0], b1 = bp[1];
            b[0]=b0.x; b[1]=b0.y; b[2]=b0.z; b[3]=b0.w;
            b[4]=b1.x; b[5]=b1.y; b[6]=b1.z; b[7]=b1.w;
        } else {
            #pragma unroll
            for (int j = 0; j < TN; j++) b[j] = sW[k * NOUT + tx * TN + j];
        }
        #pragma unroll
        for (int i = 0; i < 4; i++)
            #pragma unroll
            for (int j = 0; j < TN; j++) acc[i][j] = fmaf(a[i], b[j], acc[i][j]);
    }

    // store H
    #pragma unroll
    for (int i = 0; i < 4; i++) {
        int gr = row0 + ty * 4 + i;
        if (gr < n) {
            #pragma unroll
            for (int j = 0; j < TN; j++)
                H[(size_t)gr * NOUT + tx * TN + j] = acc[i][j];
        }
    }

    // fused attention dot products: per row, per head
    float av[TN], dv[TN];
    #pragma unroll
    for (int j = 0; j < TN; j++) {
        av[j] = attS[tx * TN + j];
        dv[j] = attD[tx * TN + j];
    }
    #pragma unroll
    for (int i = 0; i < 4; i++) {
        float ps = 0.f, pd = 0.f;
        #pragma unroll
        for (int j = 0; j < TN; j++) {
            ps = fmaf(acc[i][j], av[j], ps);
            pd = fmaf(acc[i][j], dv[j], pd);
        }
        #pragma unroll
        for (int o = 1; o < 8; o <<= 1) {
            ps += __shfl_xor_sync(FULLM, ps, o);
            pd += __shfl_xor_sync(FULLM, pd, o);
        }
        float ps8 = __shfl_xor_sync(FULLM, ps, 8);
        float pd8 = __shfl_xor_sync(FULLM, pd, 8);
        int gr = row0 + ty * 4 + i;
        if (tx == 0 && gr < n) {
            AS[gr] = make_float2(ps, ps8);   // (head0, head1)
            AD[gr] = make_float2(pd, pd8);
        }
    }
}

// ---- layer-1 gather: warp/node, edge-parallel attention, fused BN stats ----
__global__ __launch_bounds__(256)
void gather1_k(const int* __restrict__ rowptr, const int* __restrict__ col,
               const float2* __restrict__ AS, const float2* __restrict__ AD,
               const float* __restrict__ H, const float* __restrict__ b1,
               float* __restrict__ OUT, float* __restrict__ colsum,
               float* __restrict__ colsq, int n)
{
    __shared__ float bs[128], bq[128];
    const int tid = threadIdx.x;
    if (tid < 128) { bs[tid] = 0.f; bq[tid] = 0.f; }
    __syncthreads();

    const int lane = tid & 31;
    const int i = (blockIdx.x * 256 + tid) >> 5;
    if (i < n) {
        const bool hs = lane >= 16;
        const float2 adv = AD[i];
        float4 acc = make_float4(0.f, 0.f, 0.f, 0.f);
        float den0 = 0.f, den1 = 0.f;
        const int beg = rowptr[i], end = rowptr[i + 1];

        for (int base = beg; base < end; base += 32) {
            const int rem = end - base;
            const int m = rem < 32 ? rem : 32;
            int sl = 0; float w0 = 0.f, w1 = 0.f;
            if (lane < m) {
                sl = __ldg(col + base + lane);
                const float2 asv = __ldg(AS + sl);
                float a0 = asv.x + adv.x; a0 = a0 > 0.f ? a0 : NEG_SLOPE * a0;
                float a1 = asv.y + adv.y; a1 = a1 > 0.f ? a1 : NEG_SLOPE * a1;
                w0 = __expf(a0); w1 = __expf(a1);
            }
            den0 += w0; den1 += w1;
            for (int j = 0; j < m; j += 4) {
                int   sj[4]; float wj[4]; float4 v[4];
                #pragma unroll
                for (int u = 0; u < 4; u++) {
                    sj[u] = __shfl_sync(FULLM, sl, j + u);
                    float a0j = __shfl_sync(FULLM, w0, j + u);
                    float a1j = __shfl_sync(FULLM, w1, j + u);
                    wj[u] = hs ? a1j : a0j;      // 0 for padded slots
                    v[u] = *reinterpret_cast<const float4*>(H + (size_t)sj[u] * 128 + lane * 4);
                }
                #pragma unroll
                for (int u = 0; u < 4; u++) {
                    acc.x = fmaf(wj[u], v[u].x, acc.x);
                    acc.y = fmaf(wj[u], v[u].y, acc.y);
                    acc.z = fmaf(wj[u], v[u].z, acc.z);
                    acc.w = fmaf(wj[u], v[u].w, acc.w);
                }
            }
        }
        // reduce den over lanes
        #pragma unroll
        for (int o = 16; o > 0; o >>= 1) {
            den0 += __shfl_xor_sync(FULLM, den0, o);
            den1 += __shfl_xor_sync(FULLM, den1, o);
        }
        // self loop
        {
            const float2 asv = AS[i];
            float a0 = asv.x + adv.x; a0 = a0 > 0.f ? a0 : NEG_SLOPE * a0;
            float a1 = asv.y + adv.y; a1 = a1 > 0.f ? a1 : NEG_SLOPE * a1;
            const float w0 = __expf(a0), w1 = __expf(a1);
            den0 += w0; den1 += w1;
            const float w = hs ? w1 : w0;
            const float4 v = *reinterpret_cast<const float4*>(H + (size_t)i * 128 + lane * 4);
            acc.x = fmaf(w, v.x, acc.x); acc.y = fmaf(w, v.y, acc.y);
            acc.z = fmaf(w, v.z, acc.z); acc.w = fmaf(w, v.w, acc.w);
        }
        const float inv = 1.0f / (hs ? den1 : den0);
        const float4 bv = *reinterpret_cast<const float4*>(b1 + lane * 4);
        float4 o;
        o.x = acc.x * inv + bv.x; o.y = acc.y * inv + bv.y;
        o.z = acc.z * inv + bv.z; o.w = acc.w * inv + bv.w;
        *reinterpret_cast<float4*>(OUT + (size_t)i * 128 + lane * 4) = o;
        // fused BN stats (block-local)
        atomicAdd(&bs[lane * 4 + 0], o.x); atomicAdd(&bq[lane * 4 + 0], o.x * o.x);
        atomicAdd(&bs[lane * 4 + 1], o.y); atomicAdd(&bq[lane * 4 + 1], o.y * o.y);
        atomicAdd(&bs[lane * 4 + 2], o.z); atomicAdd(&bq[lane * 4 + 2], o.z * o.z);
        atomicAdd(&bs[lane * 4 + 3], o.w); atomicAdd(&bq[lane * 4 + 3], o.w * o.w);
    }
    __syncthreads();
    if (tid < 128) {
        atomicAdd(&colsum[tid], bs[tid]);
        atomicAdd(&colsq[tid],  bq[tid]);
    }
}

__global__ void bnfold_k(const float* __restrict__ colsum, const float* __restrict__ colsq,
                         const float* __restrict__ gamma, const float* __restrict__ beta,
                         float* __restrict__ scale, float* __restrict__ shift, int n)
{
    const int t = threadIdx.x;
    float inv_n = 1.0f / (float)n;
    float mean = colsum[t] * inv_n;
    float var  = colsq[t] * inv_n - mean * mean;
    float sc   = gamma[t] * rsqrtf(var + BN_EPS_F);
    scale[t] = sc;
    shift[t] = beta[t] - mean * sc;
}

// ---- layer-2 gather + head-mean + bias + log_softmax ----
__global__ __launch_bounds__(256)
void gather2_k(const int* __restrict__ rowptr, const int* __restrict__ col,
               const float2* __restrict__ AS, const float2* __restrict__ AD,
               const float* __restrict__ H, const float* __restrict__ b2,
               float* __restrict__ out, int n)
{
    const int lane = threadIdx.x & 31;
    const int i = (blockIdx.x * blockDim.x + threadIdx.x) >> 5;
    if (i >= n) return;
    const bool act = lane < 20;               // lane*4 < 80
    const bool hs  = lane >= 10;              // lane*4 >= 40 (head1)
    const float2 adv = AD[i];

    float4 acc = make_float4(0.f, 0.f, 0.f, 0.f);
    float den0 = 0.f, den1 = 0.f;
    const int beg = rowptr[i], end = rowptr[i + 1];

    for (int base = beg; base < end; base += 32) {
        const int rem = end - base;
        const int m = rem < 32 ? rem : 32;
        int sl = 0; float w0 = 0.f, w1 = 0.f;
        if (lane < m) {
            sl = __ldg(col + base + lane);
            const float2 asv = __ldg(AS + sl);
            float a0 = asv.x + adv.x; a0 = a0 > 0.f ? a0 : NEG_SLOPE * a0;
            float a1 = asv.y + adv.y; a1 = a1 > 0.f ? a1 : NEG_SLOPE * a1;
            w0 = __expf(a0); w1 = __expf(a1);
        }
        den0 += w0; den1 += w1;
        for (int j = 0; j < m; j += 4) {
            int sj[4]; float wj[4]; float4 v[4];
            #pragma unroll
            for (int u = 0; u < 4; u++) {
                sj[u] = __shfl_sync(FULLM, sl, j + u);
                float a0j = __shfl_sync(FULLM, w0, j + u);
                float a1j = __shfl_sync(FULLM, w1, j + u);
                wj[u] = hs ? a1j : a0j;
                v[u] = act ? *reinterpret_cast<const float4*>(H + (size_t)sj[u] * 80 + lane * 4)
                           : make_float4(0.f, 0.f, 0.f, 0.f);
            }
            #pragma unroll
            for (int u = 0; u < 4; u++) {
                acc.x = fmaf(wj[u], v[u].x, acc.x);
                acc.y = fmaf(wj[u], v[u].y, acc.y);
                acc.z = fmaf(wj[u], v[u].z, acc.z);
                acc.w = fmaf(wj[u], v[u].w, acc.w);
            }
        }
    }
    #pragma unroll
    for (int o = 16; o > 0; o >>= 1) {
        den0 += __shfl_xor_sync(FULLM, den0, o);
        den1 += __shfl_xor_sync(FULLM, den1, o);
    }
    // self loop
    {
        const float2 asv = AS[i];
        float a0 = asv.x + adv.x; a0 = a0 > 0.f ? a0 : NEG_SLOPE * a0;
        float a1 = asv.y + adv.y; a1 = a1 > 0.f ? a1 : NEG_SLOPE * a1;
        const float w0 = __expf(a0), w1 = __expf(a1);
        den0 += w0; den1 += w1;
        if (act) {
            const float w = hs ? w1 : w0;
            const float4 v = *reinterpret_cast<const float4*>(H + (size_t)i * 80 + lane * 4);
            acc.x = fmaf(w, v.x, acc.x); acc.y = fmaf(w, v.y, acc.y);
            acc.z = fmaf(w, v.z, acc.z); acc.w = fmaf(w, v.w, acc.w);
        }
    }
    const float inv = 1.0f / (hs ? den1 : den0);
    float4 v;
    v.x = acc.x * inv; v.y = acc.y * inv; v.z = acc.z * inv; v.w = acc.w * inv;

    // head mean: lanes 0..9 pair with lanes 10..19
    float4 o;
    o.x = __shfl_sync(FULLM, v.x, lane + 10);
    o.y = __shfl_sync(FULLM, v.y, lane + 10);
    o.z = __shfl_sync(FULLM, v.z, lane + 10);
    o.w = __shfl_sync(FULLM, v.w, lane + 10);

    float4 m = make_float4(-1e30f, -1e30f, -1e30f, -1e30f);
    if (lane < 10) {
        const float4 bv = *reinterpret_cast<const float4*>(b2 + lane * 4);
        m.x = 0.5f * (v.x + o.x) + bv.x;
        m.y = 0.5f * (v.y + o.y) + bv.y;
        m.z = 0.5f * (v.z + o.z) + bv.z;
        m.w = 0.5f * (v.w + o.w) + bv.w;
    }
    float mm = fmaxf(fmaxf(m.x, m.y), fmaxf(m.z, m.w));
    #pragma unroll
    for (int off = 16; off > 0; off >>= 1)
        mm = fmaxf(mm, __shfl_xor_sync(FULLM, mm, off));
    float ssum = 0.f;
    if (lane < 10)
        ssum = __expf(m.x - mm) + __expf(m.y - mm) + __expf(m.z - mm) + __expf(m.w - mm);
    #pragma unroll
    for (int off = 16; off > 0; off >>= 1)
        ssum += __shfl_xor_sync(FULLM, ssum, off);
    const float lse = mm + __logf(ssum);

    if (lane < 10) {
        float4 r;
        r.x = m.x - lse; r.y = m.y - lse; r.z = m.z - lse; r.w = m.w - lse;
        *reinterpret_cast<float4*>(out + (size_t)i * 40 + lane * 4) = r;
    }
}

// ------------------------------- launcher -------------------------------
extern "C" void kernel_launch(void* const* d_in, const int* in_sizes, int n_in,
                              void* d_out, int out_size)
{
    const float* x      = (const float*)d_in[0];
    const int*   ei     = (const int*)  d_in[1];
    const float* W1     = (const float*)d_in[2];
    const float* att_s1 = (const float*)d_in[3];
    const float* att_d1 = (const float*)d_in[4];
    const float* b1     = (const float*)d_in[5];
    const float* gamma  = (const float*)d_in[6];
    const float* beta   = (const float*)d_in[7];
    const float* W2     = (const float*)d_in[8];
    const float* att_s2 = (const float*)d_in[9];
    const float* att_d2 = (const float*)d_in[10];
    const float* b2     = (const float*)d_in[11];
    float* out = (float*)d_out;

    const int n = in_sizes[0] / 128;
    const int E = in_sizes[1] / 2;
    const int* src = ei;
    const int* dst = ei + E;

    float *h1, *agg1, *h2, *colsum, *colsq, *scale, *shift;
    float2 *as1, *ad1, *as2, *ad2;
    int *deg, *incl, *rowptr, *cursor, *colarr, *bsum;
    cudaGetSymbolAddress((void**)&h1,     g_h1);
    cudaGetSymbolAddress((void**)&agg1,   g_agg1);
    cudaGetSymbolAddress((void**)&h2,     g_h2);
    cudaGetSymbolAddress((void**)&as1,    g_as1);
    cudaGetSymbolAddress((void**)&ad1,    g_ad1);
    cudaGetSymbolAddress((void**)&as2,    g_as2);
    cudaGetSymbolAddress((void**)&ad2,    g_ad2);
    cudaGetSymbolAddress((void**)&deg,    g_deg);
    cudaGetSymbolAddress((void**)&incl,   g_incl);
    cudaGetSymbolAddress((void**)&rowptr, g_rowptr);
    cudaGetSymbolAddress((void**)&cursor, g_cursor);
    cudaGetSymbolAddress((void**)&colarr, g_col);
    cudaGetSymbolAddress((void**)&bsum,   g_bsum);
    cudaGetSymbolAddress((void**)&colsum, g_colsum);
    cudaGetSymbolAddress((void**)&colsq,  g_colsq);
    cudaGetSymbolAddress((void**)&scale,  g_scale);
    cudaGetSymbolAddress((void**)&shift,  g_shift);

    const size_t smem1 = (128 * 128 + 128 * 68) * sizeof(float);  // 100352 B
    const size_t smem2 = (128 * 80  + 128 * 68) * sizeof(float);  // 75776 B
    cudaFuncSetAttribute((const void*)gemm_k<128>, cudaFuncAttributeMaxDynamicSharedMemorySize, (int)smem1);
    cudaFuncSetAttribute((const void*)gemm_k<80>,  cudaFuncAttributeMaxDynamicSharedMemorySize, (int)smem2);

    const int gb = (n + 63) / 64;         // gemm blocks
    const int wb = (n * 32 + 255) / 256;  // warp-per-node blocks
    const int nb = (n + 1023) / 1024;     // scan blocks

    // ---- CSR build (shared by both layers) ----
    zero_init_k<<<(n + 255) / 256, 256>>>(deg, colsum, colsq, n);
    hist_k<<<(E + 255) / 256, 256>>>(dst, deg, E);
    scan1_k<<<nb, 1024>>>(deg, incl, bsum, n);
    scan2_k<<<1, 128>>>(bsum, nb);
    scan3_k<<<(n + 255) / 256, 256>>>(incl, bsum, deg, rowptr, cursor, n);
    fill_k<<<(E + 255) / 256, 256>>>(src, dst, cursor, colarr, E);

    // ---- layer 1 ----
    gemm_k<128><<<gb, 256, smem1>>>(x, W1, h1, n, nullptr, nullptr,
                                    att_s1, att_d1, as1, ad1);
    gather1_k<<<wb, 256>>>(rowptr, colarr, as1, ad1, h1, b1, agg1,
                           colsum, colsq, n);

    // ---- batchnorm fold ----
    bnfold_k<<<1, 128>>>(colsum, colsq, gamma, beta, scale, shift, n);

    // ---- layer 2 (BN folded into GEMM A-load) ----
    gemm_k<80><<<gb, 256, smem2>>>(agg1, W2, h2, n, scale, shift,
                                   att_s2, att_d2, as2, ad2);
    gather2_k<<<wb, 256>>>(rowptr, colarr, as2, ad2, h2, b2, out, n);
}

// round 6
// speedup vs baseline: 1.0406x; 1.0406x over previous
#include <cuda_runtime.h>

#define NEG_SLOPE 0.2f
#define BN_EPS_F  1e-5f
#define FULLM 0xffffffffu

static constexpr int NMAX = 100000;
static constexpr int EMAX = 1700000;

// ---------------- scratch (static device globals; no allocation) ----------------
__device__ float  g_h1  [(size_t)NMAX * 128];
__device__ float  g_agg1[(size_t)NMAX * 128];
__device__ float  g_h2  [(size_t)NMAX * 80];
__device__ float2 g_as1 [NMAX];
__device__ float2 g_ad1 [NMAX];
__device__ float2 g_as2 [NMAX];
__device__ float2 g_ad2 [NMAX];
__device__ int    g_deg   [NMAX];
__device__ int    g_incl  [NMAX];
__device__ int    g_rowptr[NMAX + 1];
__device__ int    g_cursor[NMAX];
__device__ int    g_col   [EMAX];
__device__ int    g_bsum  [256];
__device__ float  g_colsum[128];
__device__ float  g_colsq [128];
__device__ float  g_scale [128];
__device__ float  g_shift [128];

// ---------------- CSR build ----------------
__global__ void zero_init_k(int* deg, float* colsum, float* colsq, int n) {
    int i = blockIdx.x * blockDim.x + threadIdx.x;
    if (i < n) deg[i] = 0;
    if (i < 128) { colsum[i] = 0.f; colsq[i] = 0.f; }
}

__global__ void hist_k(const int* __restrict__ dst, int* __restrict__ deg, int E) {
    int e = blockIdx.x * blockDim.x + threadIdx.x;
    if (e < E) atomicAdd(&deg[dst[e]], 1);
}

// per-block (1024) inclusive scan + block sums
__global__ void scan1_k(const int* __restrict__ deg, int* __restrict__ incl,
                        int* __restrict__ bsum, int n) {
    __shared__ int wsum[32];
    const int tid = threadIdx.x;
    const int gid = blockIdx.x * 1024 + tid;
    const int lane = tid & 31, w = tid >> 5;
    int x = (gid < n) ? deg[gid] : 0;
    #pragma unroll
    for (int o = 1; o < 32; o <<= 1) {
        int t = __shfl_up_sync(FULLM, x, o);
        if (lane >= o) x += t;
    }
    if (lane == 31) wsum[w] = x;
    __syncthreads();
    if (w == 0) {
        int y = wsum[lane];
        #pragma unroll
        for (int o = 1; o < 32; o <<= 1) {
            int t = __shfl_up_sync(FULLM, y, o);
            if (lane >= o) y += t;
        }
        wsum[lane] = y;
    }
    __syncthreads();
    if (w > 0) x += wsum[w - 1];
    if (gid < n) incl[gid] = x;
    if (tid == 1023) bsum[blockIdx.x] = x;
}

// parallel exclusive scan of <=128 block sums (one block, 128 threads)
__global__ void scan2_k(int* bsum, int nb) {
    __shared__ int ws[4];
    const int tid = threadIdx.x, lane = tid & 31, w = tid >> 5;
    int orig = (tid < nb) ? bsum[tid] : 0;
    int x = orig;
    #pragma unroll
    for (int o = 1; o < 32; o <<= 1) {
        int t = __shfl_up_sync(FULLM, x, o);
        if (lane >= o) x += t;
    }
    if (lane == 31) ws[w] = x;
    __syncthreads();
    int add = 0;
    #pragma unroll
    for (int k = 0; k < 4; k++) if (k < w) add += ws[k];
    if (tid < nb) bsum[tid] = x + add - orig;   // exclusive
}

// rowptr (exclusive, length n+1) + cursor
__global__ void scan3_k(const int* __restrict__ incl, const int* __restrict__ bsum,
                        const int* __restrict__ deg, int* __restrict__ rowptr,
                        int* __restrict__ cursor, int n) {
    int i = blockIdx.x * blockDim.x + threadIdx.x;
    if (i < n) {
        int v = incl[i] + bsum[i >> 10];
        rowptr[i + 1] = v;
        cursor[i] = v - deg[i];
    }
    if (i == 0) rowptr[0] = 0;
}

__global__ void fill_k(const int* __restrict__ src, const int* __restrict__ dst,
                       int* __restrict__ cursor, int* __restrict__ col, int E) {
    int e = blockIdx.x * blockDim.x + threadIdx.x;
    if (e < E) {
        int p = atomicAdd(&cursor[dst[e]], 1);
        col[p] = src[e];
    }
}

// ---- GEMM: H[n,NOUT] = X[n,128] @ W[128,NOUT], optional BN fold on X,
//      fused epilogue: AS/AD attention dot-products. A tile stored transposed. ----
template<int NOUT>
__global__ __launch_bounds__(256, 2)
void gemm_k(const float* __restrict__ X, const float* __restrict__ W,
            float* __restrict__ H, int n,
            const float* __restrict__ scale, const float* __restrict__ shift,
            const float* __restrict__ attS, const float* __restrict__ attD,
            float2* __restrict__ AS, float2* __restrict__ AD)
{
    constexpr int TN = NOUT / 16;            // 8 for 128, 5 for 80
    extern __shared__ float smem[];
    float* sW  = smem;                       // [128 * NOUT]
    float* sXT = smem + 128 * NOUT;          // [128 * 68] transposed: sXT[k*68 + r]

    const int tid = threadIdx.x;
    const int tx  = tid & 15;
    const int ty  = tid >> 4;
    const int row0 = blockIdx.x * 64;

    for (int i = tid; i < 128 * NOUT; i += 256) sW[i] = W[i];
    const bool bn = (scale != nullptr);
    for (int i = tid; i < 64 * 128; i += 256) {
        int r = i >> 7, c = i & 127;
        int gr = row0 + r;
        float v = (gr < n) ? X[(size_t)gr * 128 + c] : 0.0f;
        if (bn) v = fmaf(v, scale[c], shift[c]);
        sXT[c * 68 + r] = v;
    }
    __syncthreads();

    float acc[4][TN];
    #pragma unroll
    for (int i = 0; i < 4; i++)
        #pragma unroll
        for (int j = 0; j < TN; j++) acc[i][j] = 0.0f;

    #pragma unroll 8
    for (int k = 0; k < 128; k++) {
        float4 a4 = *reinterpret_cast<const float4*>(sXT + k * 68 + ty * 4);
        float a[4] = {a4.x, a4.y, a4.z, a4.w};
        float b[TN];
        if constexpr (TN == 8) {
            const float4* bp = reinterpret_cast<const float4*>(sW + k * NOUT + tx * 8);
            float4 b0 = bp[0], b1 = bp[1];
            b[0]=b0.x; b[1]=b0.y; b[2]=b0.z; b[3]=b0.w;
            b[4]=b1.x; b[5]=b1.y; b[6]=b1.z; b[7]=b1.w;
        } else {
            #pragma unroll
            for (int j = 0; j < TN; j++) b[j] = sW[k * NOUT + tx * TN + j];
        }
        #pragma unroll
        for (int i = 0; i < 4; i++)
            #pragma unroll
            for (int j = 0; j < TN; j++) acc[i][j] = fmaf(a[i], b[j], acc[i][j]);
    }

    // store H
    #pragma unroll
    for (int i = 0; i < 4; i++) {
        int gr = row0 + ty * 4 + i;
        if (gr < n) {
            #pragma unroll
            for (int j = 0; j < TN; j++)
                H[(size_t)gr * NOUT + tx * TN + j] = acc[i][j];
        }
    }

    // fused attention dot products: per row, per head
    float av[TN], dv[TN];
    #pragma unroll
    for (int j = 0; j < TN; j++) {
        av[j] = attS[tx * TN + j];
        dv[j] = attD[tx * TN + j];
    }
    #pragma unroll
    for (int i = 0; i < 4; i++) {
        float ps = 0.f, pd = 0.f;
        #pragma unroll
        for (int j = 0; j < TN; j++) {
            ps = fmaf(acc[i][j], av[j], ps);
            pd = fmaf(acc[i][j], dv[j], pd);
        }
        #pragma unroll
        for (int o = 1; o < 8; o <<= 1) {
            ps += __shfl_xor_sync(FULLM, ps, o);
            pd += __shfl_xor_sync(FULLM, pd, o);
        }
        float ps8 = __shfl_xor_sync(FULLM, ps, 8);
        float pd8 = __shfl_xor_sync(FULLM, pd, 8);
        int gr = row0 + ty * 4 + i;
        if (tx == 0 && gr < n) {
            AS[gr] = make_float2(ps, ps8);   // (head0, head1)
            AD[gr] = make_float2(pd, pd8);
        }
    }
}

// ---- layer-1 gather (R3 loop shape): warp per dst node; CSR + self loop.
//      out = (sum_e w_e*h[src_e] + w_self*h[i]) / den + b1 ; fused BN stats ----
__global__ __launch_bounds__(256)
void gather1_k(const int* __restrict__ rowptr, const int* __restrict__ col,
               const float2* __restrict__ AS, const float2* __restrict__ AD,
               const float* __restrict__ H, const float* __restrict__ b1,
               float* __restrict__ OUT, float* __restrict__ colsum,
               float* __restrict__ colsq, int n)
{
    __shared__ float bs[128], bq[128];
    const int tid = threadIdx.x;
    if (tid < 128) { bs[tid] = 0.f; bq[tid] = 0.f; }
    __syncthreads();

    const int lane = tid & 31;
    const int i = (blockIdx.x * 256 + tid) >> 5;
    if (i < n) {
        const bool hs = lane >= 16;           // lane*4 >= 64 -> head1
        const float2 adv = AD[i];
        const float ad = hs ? adv.y : adv.x;

        float4 acc = make_float4(0.f, 0.f, 0.f, 0.f);
        float den = 0.f;
        const int beg = rowptr[i], end = rowptr[i + 1];
        #pragma unroll 4
        for (int e = beg; e < end; e++) {
            const int s = __ldg(col + e);
            const float2 asv = __ldg(AS + s);
            float a = (hs ? asv.y : asv.x) + ad;
            a = a > 0.f ? a : NEG_SLOPE * a;
            const float w = __expf(a);
            den += w;
            const float4 v = *reinterpret_cast<const float4*>(H + (size_t)s * 128 + lane * 4);
            acc.x = fmaf(w, v.x, acc.x); acc.y = fmaf(w, v.y, acc.y);
            acc.z = fmaf(w, v.z, acc.z); acc.w = fmaf(w, v.w, acc.w);
        }
        // self loop
        {
            const float2 asv = AS[i];
            float a = (hs ? asv.y : asv.x) + ad;
            a = a > 0.f ? a : NEG_SLOPE * a;
            const float w = __expf(a);
            den += w;
            const float4 v = *reinterpret_cast<const float4*>(H + (size_t)i * 128 + lane * 4);
            acc.x = fmaf(w, v.x, acc.x); acc.y = fmaf(w, v.y, acc.y);
            acc.z = fmaf(w, v.z, acc.z); acc.w = fmaf(w, v.w, acc.w);
        }
        const float inv = 1.0f / den;
        const float4 bv = *reinterpret_cast<const float4*>(b1 + lane * 4);
        float4 o;
        o.x = acc.x * inv + bv.x; o.y = acc.y * inv + bv.y;
        o.z = acc.z * inv + bv.z; o.w = acc.w * inv + bv.w;
        *reinterpret_cast<float4*>(OUT + (size_t)i * 128 + lane * 4) = o;
        // fused BN stats (block-local smem atomics)
        atomicAdd(&bs[lane * 4 + 0], o.x); atomicAdd(&bq[lane * 4 + 0], o.x * o.x);
        atomicAdd(&bs[lane * 4 + 1], o.y); atomicAdd(&bq[lane * 4 + 1], o.y * o.y);
        atomicAdd(&bs[lane * 4 + 2], o.z); atomicAdd(&bq[lane * 4 + 2], o.z * o.z);
        atomicAdd(&bs[lane * 4 + 3], o.w); atomicAdd(&bq[lane * 4 + 3], o.w * o.w);
    }
    __syncthreads();
    if (tid < 128) {
        atomicAdd(&colsum[tid], bs[tid]);
        atomicAdd(&colsq[tid],  bq[tid]);
    }
}

__global__ void bnfold_k(const float* __restrict__ colsum, const float* __restrict__ colsq,
                         const float* __restrict__ gamma, const float* __restrict__ beta,
                         float* __restrict__ scale, float* __restrict__ shift, int n)
{
    const int t = threadIdx.x;
    float inv_n = 1.0f / (float)n;
    float mean = colsum[t] * inv_n;
    float var  = colsq[t] * inv_n - mean * mean;
    float sc   = gamma[t] * rsqrtf(var + BN_EPS_F);
    scale[t] = sc;
    shift[t] = beta[t] - mean * sc;
}

// ---- layer-2 gather (R3 loop shape) + head-mean + bias + log_softmax ----
__global__ __launch_bounds__(256)
void gather2_k(const int* __restrict__ rowptr, const int* __restrict__ col,
               const float2* __restrict__ AS, const float2* __restrict__ AD,
               const float* __restrict__ H, const float* __restrict__ b2,
               float* __restrict__ out, int n)
{
    const int lane = threadIdx.x & 31;
    const int i = (blockIdx.x * blockDim.x + threadIdx.x) >> 5;
    if (i >= n) return;
    const bool act = lane < 20;               // lane*4 < 80
    const bool hs  = lane >= 10;              // lane*4 >= 40 (head1)
    const float2 adv = AD[i];
    const float ad = hs ? adv.y : adv.x;

    float4 acc = make_float4(0.f, 0.f, 0.f, 0.f);
    float den = 0.f;
    const int beg = rowptr[i], end = rowptr[i + 1];
    #pragma unroll 4
    for (int e = beg; e < end; e++) {
        const int s = __ldg(col + e);
        const float2 asv = __ldg(AS + s);
        float a = (hs ? asv.y : asv.x) + ad;
        a = a > 0.f ? a : NEG_SLOPE * a;
        const float w = __expf(a);
        den += w;
        if (act) {
            const float4 v = *reinterpret_cast<const float4*>(H + (size_t)s * 80 + lane * 4);
            acc.x = fmaf(w, v.x, acc.x); acc.y = fmaf(w, v.y, acc.y);
            acc.z = fmaf(w, v.z, acc.z); acc.w = fmaf(w, v.w, acc.w);
        }
    }
    // self loop
    {
        const float2 asv = AS[i];
        float a = (hs ? asv.y : asv.x) + ad;
        a = a > 0.f ? a : NEG_SLOPE * a;
        const float w = __expf(a);
        den += w;
        if (act) {
            const float4 v = *reinterpret_cast<const float4*>(H + (size_t)i * 80 + lane * 4);
            acc.x = fmaf(w, v.x, acc.x); acc.y = fmaf(w, v.y, acc.y);
            acc.z = fmaf(w, v.z, acc.z); acc.w = fmaf(w, v.w, acc.w);
        }
    }
    const float inv = 1.0f / den;
    float4 v;
    v.x = acc.x * inv; v.y = acc.y * inv; v.z = acc.z * inv; v.w = acc.w * inv;

    // head mean: lanes 0..9 pair with lanes 10..19
    float4 o;
    o.x = __shfl_sync(FULLM, v.x, lane + 10);
    o.y = __shfl_sync(FULLM, v.y, lane + 10);
    o.z = __shfl_sync(FULLM, v.z, lane + 10);
    o.w = __shfl_sync(FULLM, v.w, lane + 10);

    float4 m = make_float4(-1e30f, -1e30f, -1e30f, -1e30f);
    if (lane < 10) {
        const float4 bv = *reinterpret_cast<const float4*>(b2 + lane * 4);
        m.x = 0.5f * (v.x + o.x) + bv.x;
        m.y = 0.5f * (v.y + o.y) + bv.y;
        m.z = 0.5f * (v.z + o.z) + bv.z;
        m.w = 0.5f * (v.w + o.w) + bv.w;
    }
    float mm = fmaxf(fmaxf(m.x, m.y), fmaxf(m.z, m.w));
    #pragma unroll
    for (int off = 16; off > 0; off >>= 1)
        mm = fmaxf(mm, __shfl_xor_sync(FULLM, mm, off));
    float ssum = 0.f;
    if (lane < 10)
        ssum = __expf(m.x - mm) + __expf(m.y - mm) + __expf(m.z - mm) + __expf(m.w - mm);
    #pragma unroll
    for (int off = 16; off > 0; off >>= 1)
        ssum += __shfl_xor_sync(FULLM, ssum, off);
    const float lse = mm + __logf(ssum);

    if (lane < 10) {
        float4 r;
        r.x = m.x - lse; r.y = m.y - lse; r.z = m.z - lse; r.w = m.w - lse;
        *reinterpret_cast<float4*>(out + (size_t)i * 40 + lane * 4) = r;
    }
}

// ------------------------------- launcher -------------------------------
extern "C" void kernel_launch(void* const* d_in, const int* in_sizes, int n_in,
                              void* d_out, int out_size)
{
    const float* x      = (const float*)d_in[0];
    const int*   ei     = (const int*)  d_in[1];
    const float* W1     = (const float*)d_in[2];
    const float* att_s1 = (const float*)d_in[3];
    const float* att_d1 = (const float*)d_in[4];
    const float* b1     = (const float*)d_in[5];
    const float* gamma  = (const float*)d_in[6];
    const float* beta   = (const float*)d_in[7];
    const float* W2     = (const float*)d_in[8];
    const float* att_s2 = (const float*)d_in[9];
    const float* att_d2 = (const float*)d_in[10];
    const float* b2     = (const float*)d_in[11];
    float* out = (float*)d_out;

    const int n = in_sizes[0] / 128;
    const int E = in_sizes[1] / 2;
    const int* src = ei;
    const int* dst = ei + E;

    float *h1, *agg1, *h2, *colsum, *colsq, *scale, *shift;
    float2 *as1, *ad1, *as2, *ad2;
    int *deg, *incl, *rowptr, *cursor, *colarr, *bsum;
    cudaGetSymbolAddress((void**)&h1,     g_h1);
    cudaGetSymbolAddress((void**)&agg1,   g_agg1);
    cudaGetSymbolAddress((void**)&h2,     g_h2);
    cudaGetSymbolAddress((void**)&as1,    g_as1);
    cudaGetSymbolAddress((void**)&ad1,    g_ad1);
    cudaGetSymbolAddress((void**)&as2,    g_as2);
    cudaGetSymbolAddress((void**)&ad2,    g_ad2);
    cudaGetSymbolAddress((void**)&deg,    g_deg);
    cudaGetSymbolAddress((void**)&incl,   g_incl);
    cudaGetSymbolAddress((void**)&rowptr, g_rowptr);
    cudaGetSymbolAddress((void**)&cursor, g_cursor);
    cudaGetSymbolAddress((void**)&colarr, g_col);
    cudaGetSymbolAddress((void**)&bsum,   g_bsum);
    cudaGetSymbolAddress((void**)&colsum, g_colsum);
    cudaGetSymbolAddress((void**)&colsq,  g_colsq);
    cudaGetSymbolAddress((void**)&scale,  g_scale);
    cudaGetSymbolAddress((void**)&shift,  g_shift);

    const size_t smem1 = (128 * 128 + 128 * 68) * sizeof(float);  // 100352 B
    const size_t smem2 = (128 * 80  + 128 * 68) * sizeof(float);  // 75776 B
    cudaFuncSetAttribute((const void*)gemm_k<128>, cudaFuncAttributeMaxDynamicSharedMemorySize, (int)smem1);
    cudaFuncSetAttribute((const void*)gemm_k<80>,  cudaFuncAttributeMaxDynamicSharedMemorySize, (int)smem2);

    const int gb = (n + 63) / 64;         // gemm blocks
    const int wb = (n * 32 + 255) / 256;  // warp-per-node blocks
    const int nb = (n + 1023) / 1024;     // scan blocks

    // ---- CSR build (shared by both layers) ----
    zero_init_k<<<(n + 255) / 256, 256>>>(deg, colsum, colsq, n);
    hist_k<<<(E + 255) / 256, 256>>>(dst, deg, E);
    scan1_k<<<nb, 1024>>>(deg, incl, bsum, n);
    scan2_k<<<1, 128>>>(bsum, nb);
    scan3_k<<<(n + 255) / 256, 256>>>(incl, bsum, deg, rowptr, cursor, n);
    fill_k<<<(E + 255) / 256, 256>>>(src, dst, cursor, colarr, E);

    // ---- layer 1 ----
    gemm_k<128><<<gb, 256, smem1>>>(x, W1, h1, n, nullptr, nullptr,
                                    att_s1, att_d1, as1, ad1);
    gather1_k<<<wb, 256>>>(rowptr, colarr, as1, ad1, h1, b1, agg1,
                           colsum, colsq, n);

    // ---- batchnorm fold ----
    bnfold_k<<<1, 128>>>(colsum, colsq, gamma, beta, scale, shift, n);

    // ---- layer 2 (BN folded into GEMM A-load) ----
    gemm_k<80><<<gb, 256, smem2>>>(agg1, W2, h2, n, scale, shift,
                                   att_s2, att_d2, as2, ad2);
    gather2_k<<<wb, 256>>>(rowptr, colarr, as2, ad2, h2, b2, out, n);
}

// round 7
// speedup vs baseline: 1.0407x; 1.0001x over previous
#include <cuda_runtime.h>

#define NEG_SLOPE 0.2f
#define BN_EPS_F  1e-5f
#define FULLM 0xffffffffu

static constexpr int NMAX = 100000;
static constexpr int EMAX = 1700000;

// ---------------- scratch (static device globals; no allocation) ----------------
__device__ float  g_h1  [(size_t)NMAX * 128];
__device__ float  g_agg1[(size_t)NMAX * 128];
__device__ float  g_h2  [(size_t)NMAX * 80];
__device__ float2 g_as1 [NMAX];
__device__ float2 g_ad1 [NMAX];
__device__ float2 g_as2 [NMAX];
__device__ float2 g_ad2 [NMAX];
__device__ int    g_deg   [NMAX];
__device__ int    g_incl  [NMAX];
__device__ int    g_rowptr[NMAX + 1];
__device__ int    g_cursor[NMAX];
__device__ int    g_col   [EMAX];
__device__ int    g_bsum  [256];
__device__ float  g_colsum[128];
__device__ float  g_colsq [128];
__device__ float  g_scale [128];
__device__ float  g_shift [128];

// ---------------- CSR build ----------------
__global__ void zero_init_k(int* deg, float* colsum, float* colsq, int n) {
    int i = blockIdx.x * blockDim.x + threadIdx.x;
    if (i < n) deg[i] = 0;
    if (i < 128) { colsum[i] = 0.f; colsq[i] = 0.f; }
}

__global__ void hist_k(const int* __restrict__ dst, int* __restrict__ deg, int E) {
    int e = blockIdx.x * blockDim.x + threadIdx.x;
    if (e < E) atomicAdd(&deg[dst[e]], 1);
}

// per-block (1024) inclusive scan + block sums
__global__ void scan1_k(const int* __restrict__ deg, int* __restrict__ incl,
                        int* __restrict__ bsum, int n) {
    __shared__ int wsum[32];
    const int tid = threadIdx.x;
    const int gid = blockIdx.x * 1024 + tid;
    const int lane = tid & 31, w = tid >> 5;
    int x = (gid < n) ? deg[gid] : 0;
    #pragma unroll
    for (int o = 1; o < 32; o <<= 1) {
        int t = __shfl_up_sync(FULLM, x, o);
        if (lane >= o) x += t;
    }
    if (lane == 31) wsum[w] = x;
    __syncthreads();
    if (w == 0) {
        int y = wsum[lane];
        #pragma unroll
        for (int o = 1; o < 32; o <<= 1) {
            int t = __shfl_up_sync(FULLM, y, o);
            if (lane >= o) y += t;
        }
        wsum[lane] = y;
    }
    __syncthreads();
    if (w > 0) x += wsum[w - 1];
    if (gid < n) incl[gid] = x;
    if (tid == 1023) bsum[blockIdx.x] = x;
}

// parallel exclusive scan of <=128 block sums (one block, 128 threads)
__global__ void scan2_k(int* bsum, int nb) {
    __shared__ int ws[4];
    const int tid = threadIdx.x, lane = tid & 31, w = tid >> 5;
    int orig = (tid < nb) ? bsum[tid] : 0;
    int x = orig;
    #pragma unroll
    for (int o = 1; o < 32; o <<= 1) {
        int t = __shfl_up_sync(FULLM, x, o);
        if (lane >= o) x += t;
    }
    if (lane == 31) ws[w] = x;
    __syncthreads();
    int add = 0;
    #pragma unroll
    for (int k = 0; k < 4; k++) if (k < w) add += ws[k];
    if (tid < nb) bsum[tid] = x + add - orig;   // exclusive
}

// rowptr (exclusive, length n+1) + cursor
__global__ void scan3_k(const int* __restrict__ incl, const int* __restrict__ bsum,
                        const int* __restrict__ deg, int* __restrict__ rowptr,
                        int* __restrict__ cursor, int n) {
    int i = blockIdx.x * blockDim.x + threadIdx.x;
    if (i < n) {
        int v = incl[i] + bsum[i >> 10];
        rowptr[i + 1] = v;
        cursor[i] = v - deg[i];
    }
    if (i == 0) rowptr[0] = 0;
}

__global__ void fill_k(const int* __restrict__ src, const int* __restrict__ dst,
                       int* __restrict__ cursor, int* __restrict__ col, int E) {
    int e = blockIdx.x * blockDim.x + threadIdx.x;
    if (e < E) {
        int p = atomicAdd(&cursor[dst[e]], 1);
        col[p] = src[e];
    }
}

// ---- GEMM (R3 layout): H[n,NOUT] = X[n,128] @ W[128,NOUT], optional BN fold,
//      fused epilogue: AS/AD attention dot-products ----
template<int NOUT>
__global__ __launch_bounds__(256, 2)
void gemm_k(const float* __restrict__ X, const float* __restrict__ W,
            float* __restrict__ H, int n,
            const float* __restrict__ scale, const float* __restrict__ shift,
            const float* __restrict__ attS, const float* __restrict__ attD,
            float2* __restrict__ AS, float2* __restrict__ AD)
{
    constexpr int TN = NOUT / 16;            // 8 for 128, 5 for 80
    extern __shared__ float smem[];
    float* sW = smem;                        // [128 * NOUT]
    float* sX = smem + 128 * NOUT;           // [64 * 132]

    const int tid = threadIdx.x;
    const int tx  = tid & 15;
    const int ty  = tid >> 4;
    const int row0 = blockIdx.x * 64;

    for (int i = tid; i < 128 * NOUT; i += 256) sW[i] = W[i];
    const bool bn = (scale != nullptr);
    for (int i = tid; i < 64 * 128; i += 256) {
        int r = i >> 7, c = i & 127;
        int gr = row0 + r;
        float v = (gr < n) ? X[(size_t)gr * 128 + c] : 0.0f;
        if (bn) v = fmaf(v, scale[c], shift[c]);
        sX[r * 132 + c] = v;
    }
    __syncthreads();

    float acc[4][TN];
    #pragma unroll
    for (int i = 0; i < 4; i++)
        #pragma unroll
        for (int j = 0; j < TN; j++) acc[i][j] = 0.0f;

    #pragma unroll 8
    for (int k = 0; k < 128; k++) {
        float a[4];
        #pragma unroll
        for (int i = 0; i < 4; i++) a[i] = sX[(ty * 4 + i) * 132 + k];
        float b[TN];
        if constexpr (TN == 8) {
            const float4* bp = reinterpret_cast<const float4*>(sW + k * NOUT + tx * 8);
            float4 b0 = bp[0], b1 = bp[1];
            b[0]=b0.x; b[1]=b0.y; b[2]=b0.z; b[3]=b0.w;
            b[4]=b1.x; b[5]=b1.y; b[6]=b1.z; b[7]=b1.w;
        } else {
            #pragma unroll
            for (int j = 0; j < TN; j++) b[j] = sW[k * NOUT + tx * TN + j];
        }
        #pragma unroll
        for (int i = 0; i < 4; i++)
            #pragma unroll
            for (int j = 0; j < TN; j++) acc[i][j] = fmaf(a[i], b[j], acc[i][j]);
    }

    // store H
    #pragma unroll
    for (int i = 0; i < 4; i++) {
        int gr = row0 + ty * 4 + i;
        if (gr < n) {
            #pragma unroll
            for (int j = 0; j < TN; j++)
                H[(size_t)gr * NOUT + tx * TN + j] = acc[i][j];
        }
    }

    // fused attention dot products: per row, per head
    float av[TN], dv[TN];
    #pragma unroll
    for (int j = 0; j < TN; j++) {
        av[j] = attS[tx * TN + j];
        dv[j] = attD[tx * TN + j];
    }
    #pragma unroll
    for (int i = 0; i < 4; i++) {
        float ps = 0.f, pd = 0.f;
        #pragma unroll
        for (int j = 0; j < TN; j++) {
            ps = fmaf(acc[i][j], av[j], ps);
            pd = fmaf(acc[i][j], dv[j], pd);
        }
        #pragma unroll
        for (int o = 1; o < 8; o <<= 1) {
            ps += __shfl_xor_sync(FULLM, ps, o);
            pd += __shfl_xor_sync(FULLM, pd, o);
        }
        float ps8 = __shfl_xor_sync(FULLM, ps, 8);
        float pd8 = __shfl_xor_sync(FULLM, pd, 8);
        int gr = row0 + ty * 4 + i;
        if (tx == 0 && gr < n) {
            AS[gr] = make_float2(ps, ps8);   // (head0, head1)
            AD[gr] = make_float2(pd, pd8);
        }
    }
}

// ---- layer-1 gather (R3 loop): warp per dst node; CSR + self loop;
//      fused BN stats epilogue ----
__global__ __launch_bounds__(256)
void gather1_k(const int* __restrict__ rowptr, const int* __restrict__ col,
               const float2* __restrict__ AS, const float2* __restrict__ AD,
               const float* __restrict__ H, const float* __restrict__ b1,
               float* __restrict__ OUT, float* __restrict__ colsum,
               float* __restrict__ colsq, int n)
{
    __shared__ float bs[128], bq[128];
    const int tid = threadIdx.x;
    if (tid < 128) { bs[tid] = 0.f; bq[tid] = 0.f; }
    __syncthreads();

    const int lane = tid & 31;
    const int i = (blockIdx.x * 256 + tid) >> 5;
    if (i < n) {
        const bool hs = lane >= 16;           // lane*4 >= 64 -> head1
        const float2 adv = AD[i];
        const float ad = hs ? adv.y : adv.x;

        float4 acc = make_float4(0.f, 0.f, 0.f, 0.f);
        float den = 0.f;
        const int beg = rowptr[i], end = rowptr[i + 1];
        #pragma unroll 4
        for (int e = beg; e < end; e++) {
            const int s = __ldg(col + e);
            const float2 asv = __ldg(AS + s);
            float a = (hs ? asv.y : asv.x) + ad;
            a = a > 0.f ? a : NEG_SLOPE * a;
            const float w = __expf(a);
            den += w;
            const float4 v = *reinterpret_cast<const float4*>(H + (size_t)s * 128 + lane * 4);
            acc.x = fmaf(w, v.x, acc.x); acc.y = fmaf(w, v.y, acc.y);
            acc.z = fmaf(w, v.z, acc.z); acc.w = fmaf(w, v.w, acc.w);
        }
        // self loop
        {
            const float2 asv = AS[i];
            float a = (hs ? asv.y : asv.x) + ad;
            a = a > 0.f ? a : NEG_SLOPE * a;
            const float w = __expf(a);
            den += w;
            const float4 v = *reinterpret_cast<const float4*>(H + (size_t)i * 128 + lane * 4);
            acc.x = fmaf(w, v.x, acc.x); acc.y = fmaf(w, v.y, acc.y);
            acc.z = fmaf(w, v.z, acc.z); acc.w = fmaf(w, v.w, acc.w);
        }
        const float inv = 1.0f / den;
        const float4 bv = *reinterpret_cast<const float4*>(b1 + lane * 4);
        float4 o;
        o.x = acc.x * inv + bv.x; o.y = acc.y * inv + bv.y;
        o.z = acc.z * inv + bv.z; o.w = acc.w * inv + bv.w;
        *reinterpret_cast<float4*>(OUT + (size_t)i * 128 + lane * 4) = o;
        // fused BN stats (block-local smem atomics; addresses distinct per warp)
        atomicAdd(&bs[lane * 4 + 0], o.x); atomicAdd(&bq[lane * 4 + 0], o.x * o.x);
        atomicAdd(&bs[lane * 4 + 1], o.y); atomicAdd(&bq[lane * 4 + 1], o.y * o.y);
        atomicAdd(&bs[lane * 4 + 2], o.z); atomicAdd(&bq[lane * 4 + 2], o.z * o.z);
        atomicAdd(&bs[lane * 4 + 3], o.w); atomicAdd(&bq[lane * 4 + 3], o.w * o.w);
    }
    __syncthreads();
    if (tid < 128) {
        atomicAdd(&colsum[tid], bs[tid]);
        atomicAdd(&colsq[tid],  bq[tid]);
    }
}

__global__ void bnfold_k(const float* __restrict__ colsum, const float* __restrict__ colsq,
                         const float* __restrict__ gamma, const float* __restrict__ beta,
                         float* __restrict__ scale, float* __restrict__ shift, int n)
{
    const int t = threadIdx.x;
    float inv_n = 1.0f / (float)n;
    float mean = colsum[t] * inv_n;
    float var  = colsq[t] * inv_n - mean * mean;
    float sc   = gamma[t] * rsqrtf(var + BN_EPS_F);
    scale[t] = sc;
    shift[t] = beta[t] - mean * sc;
}

// ---- layer-2 gather (R3 loop) + head-mean + bias + log_softmax ----
__global__ __launch_bounds__(256)
void gather2_k(const int* __restrict__ rowptr, const int* __restrict__ col,
               const float2* __restrict__ AS, const float2* __restrict__ AD,
               const float* __restrict__ H, const float* __restrict__ b2,
               float* __restrict__ out, int n)
{
    const int lane = threadIdx.x & 31;
    const int i = (blockIdx.x * blockDim.x + threadIdx.x) >> 5;
    if (i >= n) return;
    const bool act = lane < 20;               // lane*4 < 80
    const bool hs  = lane >= 10;              // lane*4 >= 40 (head1)
    const float2 adv = AD[i];
    const float ad = hs ? adv.y : adv.x;

    float4 acc = make_float4(0.f, 0.f, 0.f, 0.f);
    float den = 0.f;
    const int beg = rowptr[i], end = rowptr[i + 1];
    #pragma unroll 4
    for (int e = beg; e < end; e++) {
        const int s = __ldg(col + e);
        const float2 asv = __ldg(AS + s);
        float a = (hs ? asv.y : asv.x) + ad;
        a = a > 0.f ? a : NEG_SLOPE * a;
        const float w = __expf(a);
        den += w;
        if (act) {
            const float4 v = *reinterpret_cast<const float4*>(H + (size_t)s * 80 + lane * 4);
            acc.x = fmaf(w, v.x, acc.x); acc.y = fmaf(w, v.y, acc.y);
            acc.z = fmaf(w, v.z, acc.z); acc.w = fmaf(w, v.w, acc.w);
        }
    }
    // self loop
    {
        const float2 asv = AS[i];
        float a = (hs ? asv.y : asv.x) + ad;
        a = a > 0.f ? a : NEG_SLOPE * a;
        const float w = __expf(a);
        den += w;
        if (act) {
            const float4 v = *reinterpret_cast<const float4*>(H + (size_t)i * 80 + lane * 4);
            acc.x = fmaf(w, v.x, acc.x); acc.y = fmaf(w, v.y, acc.y);
            acc.z = fmaf(w, v.z, acc.z); acc.w = fmaf(w, v.w, acc.w);
        }
    }
    const float inv = 1.0f / den;
    float4 v;
    v.x = acc.x * inv; v.y = acc.y * inv; v.z = acc.z * inv; v.w = acc.w * inv;

    // head mean: lanes 0..9 pair with lanes 10..19
    float4 o;
    o.x = __shfl_sync(FULLM, v.x, lane + 10);
    o.y = __shfl_sync(FULLM, v.y, lane + 10);
    o.z = __shfl_sync(FULLM, v.z, lane + 10);
    o.w = __shfl_sync(FULLM, v.w, lane + 10);

    float4 m = make_float4(-1e30f, -1e30f, -1e30f, -1e30f);
    if (lane < 10) {
        const float4 bv = *reinterpret_cast<const float4*>(b2 + lane * 4);
        m.x = 0.5f * (v.x + o.x) + bv.x;
        m.y = 0.5f * (v.y + o.y) + bv.y;
        m.z = 0.5f * (v.z + o.z) + bv.z;
        m.w = 0.5f * (v.w + o.w) + bv.w;
    }
    float mm = fmaxf(fmaxf(m.x, m.y), fmaxf(m.z, m.w));
    #pragma unroll
    for (int off = 16; off > 0; off >>= 1)
        mm = fmaxf(mm, __shfl_xor_sync(FULLM, mm, off));
    float ssum = 0.f;
    if (lane < 10)
        ssum = __expf(m.x - mm) + __expf(m.y - mm) + __expf(m.z - mm) + __expf(m.w - mm);
    #pragma unroll
    for (int off = 16; off > 0; off >>= 1)
        ssum += __shfl_xor_sync(FULLM, ssum, off);
    const float lse = mm + __logf(ssum);

    if (lane < 10) {
        float4 r;
        r.x = m.x - lse; r.y = m.y - lse; r.z = m.z - lse; r.w = m.w - lse;
        *reinterpret_cast<float4*>(out + (size_t)i * 40 + lane * 4) = r;
    }
}

// ------------------------------- launcher -------------------------------
extern "C" void kernel_launch(void* const* d_in, const int* in_sizes, int n_in,
                              void* d_out, int out_size)
{
    const float* x      = (const float*)d_in[0];
    const int*   ei     = (const int*)  d_in[1];
    const float* W1     = (const float*)d_in[2];
    const float* att_s1 = (const float*)d_in[3];
    const float* att_d1 = (const float*)d_in[4];
    const float* b1     = (const float*)d_in[5];
    const float* gamma  = (const float*)d_in[6];
    const float* beta   = (const float*)d_in[7];
    const float* W2     = (const float*)d_in[8];
    const float* att_s2 = (const float*)d_in[9];
    const float* att_d2 = (const float*)d_in[10];
    const float* b2     = (const float*)d_in[11];
    float* out = (float*)d_out;

    const int n = in_sizes[0] / 128;
    const int E = in_sizes[1] / 2;
    const int* src = ei;
    const int* dst = ei + E;

    float *h1, *agg1, *h2, *colsum, *colsq, *scale, *shift;
    float2 *as1, *ad1, *as2, *ad2;
    int *deg, *incl, *rowptr, *cursor, *colarr, *bsum;
    cudaGetSymbolAddress((void**)&h1,     g_h1);
    cudaGetSymbolAddress((void**)&agg1,   g_agg1);
    cudaGetSymbolAddress((void**)&h2,     g_h2);
    cudaGetSymbolAddress((void**)&as1,    g_as1);
    cudaGetSymbolAddress((void**)&ad1,    g_ad1);
    cudaGetSymbolAddress((void**)&as2,    g_as2);
    cudaGetSymbolAddress((void**)&ad2,    g_ad2);
    cudaGetSymbolAddress((void**)&deg,    g_deg);
    cudaGetSymbolAddress((void**)&incl,   g_incl);
    cudaGetSymbolAddress((void**)&rowptr, g_rowptr);
    cudaGetSymbolAddress((void**)&cursor, g_cursor);
    cudaGetSymbolAddress((void**)&colarr, g_col);
    cudaGetSymbolAddress((void**)&bsum,   g_bsum);
    cudaGetSymbolAddress((void**)&colsum, g_colsum);
    cudaGetSymbolAddress((void**)&colsq,  g_colsq);
    cudaGetSymbolAddress((void**)&scale,  g_scale);
    cudaGetSymbolAddress((void**)&shift,  g_shift);

    const size_t smem1 = (128 * 128 + 64 * 132) * sizeof(float);  // 99328 B
    const size_t smem2 = (128 * 80  + 64 * 132) * sizeof(float);  // 74752 B
    cudaFuncSetAttribute((const void*)gemm_k<128>, cudaFuncAttributeMaxDynamicSharedMemorySize, (int)smem1);
    cudaFuncSetAttribute((const void*)gemm_k<80>,  cudaFuncAttributeMaxDynamicSharedMemorySize, (int)smem2);

    const int gb = (n + 63) / 64;         // gemm blocks
    const int wb = (n * 32 + 255) / 256;  // warp-per-node blocks
    const int nb = (n + 1023) / 1024;     // scan blocks

    // ---- CSR build (shared by both layers) ----
    zero_init_k<<<(n + 255) / 256, 256>>>(deg, colsum, colsq, n);
    hist_k<<<(E + 255) / 256, 256>>>(dst, deg, E);
    scan1_k<<<nb, 1024>>>(deg, incl, bsum, n);
    scan2_k<<<1, 128>>>(bsum, nb);
    scan3_k<<<(n + 255) / 256, 256>>>(incl, bsum, deg, rowptr, cursor, n);
    fill_k<<<(E + 255) / 256, 256>>>(src, dst, cursor, colarr, E);

    // ---- layer 1 ----
    gemm_k<128><<<gb, 256, smem1>>>(x, W1, h1, n, nullptr, nullptr,
                                    att_s1, att_d1, as1, ad1);
    gather1_k<<<wb, 256>>>(rowptr, colarr, as1, ad1, h1, b1, agg1,
                           colsum, colsq, n);

    // ---- batchnorm fold ----
    bnfold_k<<<1, 128>>>(colsum, colsq, gamma, beta, scale, shift, n);

    // ---- layer 2 (BN folded into GEMM A-load) ----
    gemm_k<80><<<gb, 256, smem2>>>(agg1, W2, h2, n, scale, shift,
                                   att_s2, att_d2, as2, ad2);
    gather2_k<<<wb, 256>>>(rowptr, colarr, as2, ad2, h2, b2, out, n);
}

// round 8
// speedup vs baseline: 1.2232x; 1.1754x over previous
#include <cuda_runtime.h>

#define NEG_SLOPE 0.2f
#define BN_EPS_F  1e-5f
#define FULLM 0xffffffffu

static constexpr int NMAX = 100000;
static constexpr int EMAX = 1700000;

// ---------------- scratch (static device globals; no allocation) ----------------
__device__ float  g_h1  [(size_t)NMAX * 128];
__device__ float  g_agg1[(size_t)NMAX * 128];
__device__ float  g_h2  [(size_t)NMAX * 80];
__device__ float2 g_as1 [NMAX];
__device__ float2 g_ad1 [NMAX];
__device__ float2 g_as2 [NMAX];
__device__ float2 g_ad2 [NMAX];
__device__ int    g_deg   [NMAX];
__device__ int    g_incl  [NMAX];
__device__ int    g_rowptr[NMAX + 1];
__device__ int    g_cursor[NMAX];
__device__ int    g_col   [EMAX];
__device__ int    g_bsum  [256];
__device__ float  g_colsum[128];
__device__ float  g_colsq [128];
__device__ float  g_scale [128];
__device__ float  g_shift [128];

// ---------------- packed f32x2 helpers (sm_103a FFMA2 path) ----------------
__device__ __forceinline__ unsigned long long pack2(float lo, float hi) {
    unsigned long long r;
    asm("mov.b64 %0, {%1, %2};" : "=l"(r) : "f"(lo), "f"(hi));
    return r;
}
__device__ __forceinline__ void fma2(unsigned long long& d, unsigned long long a,
                                     unsigned long long b) {
    asm("fma.rn.f32x2 %0, %1, %2, %0;" : "+l"(d) : "l"(a), "l"(b));
}
__device__ __forceinline__ void unpack2(unsigned long long v, float& lo, float& hi) {
    asm("mov.b64 {%0, %1}, %2;" : "=f"(lo), "=f"(hi) : "l"(v));
}

// ---------------- CSR build ----------------
__global__ void zero_init_k(int* deg, float* colsum, float* colsq, int n) {
    int i = blockIdx.x * blockDim.x + threadIdx.x;
    if (i < n) deg[i] = 0;
    if (i < 128) { colsum[i] = 0.f; colsq[i] = 0.f; }
}

__global__ void hist_k(const int* __restrict__ dst, int* __restrict__ deg, int E) {
    int e = blockIdx.x * blockDim.x + threadIdx.x;
    if (e < E) atomicAdd(&deg[dst[e]], 1);
}

// per-block (1024) inclusive scan + block sums
__global__ void scan1_k(const int* __restrict__ deg, int* __restrict__ incl,
                        int* __restrict__ bsum, int n) {
    __shared__ int wsum[32];
    const int tid = threadIdx.x;
    const int gid = blockIdx.x * 1024 + tid;
    const int lane = tid & 31, w = tid >> 5;
    int x = (gid < n) ? deg[gid] : 0;
    #pragma unroll
    for (int o = 1; o < 32; o <<= 1) {
        int t = __shfl_up_sync(FULLM, x, o);
        if (lane >= o) x += t;
    }
    if (lane == 31) wsum[w] = x;
    __syncthreads();
    if (w == 0) {
        int y = wsum[lane];
        #pragma unroll
        for (int o = 1; o < 32; o <<= 1) {
            int t = __shfl_up_sync(FULLM, y, o);
            if (lane >= o) y += t;
        }
        wsum[lane] = y;
    }
    __syncthreads();
    if (w > 0) x += wsum[w - 1];
    if (gid < n) incl[gid] = x;
    if (tid == 1023) bsum[blockIdx.x] = x;
}

// parallel exclusive scan of <=128 block sums (one block, 128 threads)
__global__ void scan2_k(int* bsum, int nb) {
    __shared__ int ws[4];
    const int tid = threadIdx.x, lane = tid & 31, w = tid >> 5;
    int orig = (tid < nb) ? bsum[tid] : 0;
    int x = orig;
    #pragma unroll
    for (int o = 1; o < 32; o <<= 1) {
        int t = __shfl_up_sync(FULLM, x, o);
        if (lane >= o) x += t;
    }
    if (lane == 31) ws[w] = x;
    __syncthreads();
    int add = 0;
    #pragma unroll
    for (int k = 0; k < 4; k++) if (k < w) add += ws[k];
    if (tid < nb) bsum[tid] = x + add - orig;   // exclusive
}

// rowptr (exclusive, length n+1) + cursor
__global__ void scan3_k(const int* __restrict__ incl, const int* __restrict__ bsum,
                        const int* __restrict__ deg, int* __restrict__ rowptr,
                        int* __restrict__ cursor, int n) {
    int i = blockIdx.x * blockDim.x + threadIdx.x;
    if (i < n) {
        int v = incl[i] + bsum[i >> 10];
        rowptr[i + 1] = v;
        cursor[i] = v - deg[i];
    }
    if (i == 0) rowptr[0] = 0;
}

__global__ void fill_k(const int* __restrict__ src, const int* __restrict__ dst,
                       int* __restrict__ cursor, int* __restrict__ col, int E) {
    int e = blockIdx.x * blockDim.x + threadIdx.x;
    if (e < E) {
        int p = atomicAdd(&cursor[dst[e]], 1);
        col[p] = src[e];
    }
}

// ---- GEMM: H[n,NOUT] = X[n,128] @ W[128,NOUT] via packed f32x2 FMA.
//      Optional BN fold on X load; fused AS/AD attention epilogue. ----
// Column map per thread (tx = 0..15):
//   NOUT=128: cols tx*8 + j (j=0..7), pairs aligned.
//   NOUT=80 : cols tx*4 + j (j=0..3) and 64+tx (odd scalar column).
template<int NOUT>
__global__ __launch_bounds__(256, 2)
void gemm_k(const float* __restrict__ X, const float* __restrict__ W,
            float* __restrict__ H, int n,
            const float* __restrict__ scale, const float* __restrict__ shift,
            const float* __restrict__ attS, const float* __restrict__ attD,
            float2* __restrict__ AS, float2* __restrict__ AD)
{
    constexpr int TN = (NOUT == 128) ? 8 : 5;
    constexpr int NP = TN / 2;                  // 4 or 2 pairs
    constexpr bool ODD = (TN & 1) != 0;
    constexpr int HALF = NOUT / 2;              // head boundary

    extern __shared__ float smem[];
    float* sW = smem;                           // [128 * NOUT]
    float* sX = smem + 128 * NOUT;              // [64 * 132]

    const int tid = threadIdx.x;
    const int tx  = tid & 15;
    const int ty  = tid >> 4;
    const int row0 = blockIdx.x * 64;

    for (int i = tid; i < 128 * NOUT; i += 256) sW[i] = W[i];
    const bool bn = (scale != nullptr);
    for (int i = tid; i < 64 * 128; i += 256) {
        int r = i >> 7, c = i & 127;
        int gr = row0 + r;
        float v = (gr < n) ? X[(size_t)gr * 128 + c] : 0.0f;
        if (bn) v = fmaf(v, scale[c], shift[c]);
        sX[r * 132 + c] = v;
    }
    __syncthreads();

    unsigned long long acc2[4][NP];
    float acco[4];
    #pragma unroll
    for (int i = 0; i < 4; i++) {
        #pragma unroll
        for (int p = 0; p < NP; p++) acc2[i][p] = 0ull;
        acco[i] = 0.f;
    }

    #pragma unroll 8
    for (int k = 0; k < 128; k++) {
        float a[4];
        unsigned long long a2[4];
        #pragma unroll
        for (int i = 0; i < 4; i++) {
            a[i] = sX[(ty * 4 + i) * 132 + k];
            a2[i] = pack2(a[i], a[i]);
        }
        unsigned long long bp[NP];
        float bo = 0.f;
        if constexpr (NOUT == 128) {
            const float4* q = reinterpret_cast<const float4*>(sW + k * 128 + tx * 8);
            float4 b0 = q[0], b1 = q[1];
            bp[0] = pack2(b0.x, b0.y); bp[1] = pack2(b0.z, b0.w);
            bp[2] = pack2(b1.x, b1.y); bp[3] = pack2(b1.z, b1.w);
        } else {
            float4 b0 = *reinterpret_cast<const float4*>(sW + k * 80 + tx * 4);
            bp[0] = pack2(b0.x, b0.y); bp[1] = pack2(b0.z, b0.w);
            bo = sW[k * 80 + 64 + tx];
        }
        #pragma unroll
        for (int i = 0; i < 4; i++) {
            #pragma unroll
            for (int p = 0; p < NP; p++) fma2(acc2[i][p], a2[i], bp[p]);
            if constexpr (ODD) acco[i] = fmaf(a[i], bo, acco[i]);
        }
    }

    // unpack accumulators
    float acc[4][TN];
    #pragma unroll
    for (int i = 0; i < 4; i++) {
        #pragma unroll
        for (int p = 0; p < NP; p++) unpack2(acc2[i][p], acc[i][2 * p], acc[i][2 * p + 1]);
        if constexpr (ODD) acc[i][TN - 1] = acco[i];
    }

    // column index map
    int cmap[TN];
    #pragma unroll
    for (int j = 0; j < TN; j++) {
        if constexpr (NOUT == 128) cmap[j] = tx * 8 + j;
        else cmap[j] = (j < 4) ? (tx * 4 + j) : (64 + tx);
    }

    // store H
    #pragma unroll
    for (int i = 0; i < 4; i++) {
        int gr = row0 + ty * 4 + i;
        if (gr < n) {
            #pragma unroll
            for (int j = 0; j < TN; j++)
                H[(size_t)gr * NOUT + cmap[j]] = acc[i][j];
        }
    }

    // fused attention dot products, per-head accumulate then 16-lane reduce
    float av[TN], dv[TN];
    #pragma unroll
    for (int j = 0; j < TN; j++) {
        av[j] = attS[cmap[j]];
        dv[j] = attD[cmap[j]];
    }
    #pragma unroll
    for (int i = 0; i < 4; i++) {
        float ps0 = 0.f, ps1 = 0.f, pd0 = 0.f, pd1 = 0.f;
        #pragma unroll
        for (int j = 0; j < TN; j++) {
            if (cmap[j] < HALF) {
                ps0 = fmaf(acc[i][j], av[j], ps0);
                pd0 = fmaf(acc[i][j], dv[j], pd0);
            } else {
                ps1 = fmaf(acc[i][j], av[j], ps1);
                pd1 = fmaf(acc[i][j], dv[j], pd1);
            }
        }
        #pragma unroll
        for (int o = 1; o < 16; o <<= 1) {
            ps0 += __shfl_xor_sync(FULLM, ps0, o);
            ps1 += __shfl_xor_sync(FULLM, ps1, o);
            pd0 += __shfl_xor_sync(FULLM, pd0, o);
            pd1 += __shfl_xor_sync(FULLM, pd1, o);
        }
        int gr = row0 + ty * 4 + i;
        if (tx == 0 && gr < n) {
            AS[gr] = make_float2(ps0, ps1);
            AD[gr] = make_float2(pd0, pd1);
        }
    }
}

// ---- layer-1 gather (R3): warp per dst node; CSR + self loop; no barrier ----
__global__ __launch_bounds__(256)
void gather1_k(const int* __restrict__ rowptr, const int* __restrict__ col,
               const float2* __restrict__ AS, const float2* __restrict__ AD,
               const float* __restrict__ H, const float* __restrict__ b1,
               float* __restrict__ OUT, int n)
{
    const int lane = threadIdx.x & 31;
    const int i = (blockIdx.x * blockDim.x + threadIdx.x) >> 5;
    if (i >= n) return;
    const bool hs = lane >= 16;               // lane*4 >= 64 -> head1
    const float2 adv = AD[i];
    const float ad = hs ? adv.y : adv.x;

    float4 acc = make_float4(0.f, 0.f, 0.f, 0.f);
    float den = 0.f;
    const int beg = rowptr[i], end = rowptr[i + 1];
    #pragma unroll 4
    for (int e = beg; e < end; e++) {
        const int s = __ldg(col + e);
        const float2 asv = __ldg(AS + s);
        float a = (hs ? asv.y : asv.x) + ad;
        a = a > 0.f ? a : NEG_SLOPE * a;
        const float w = __expf(a);
        den += w;
        const float4 v = *reinterpret_cast<const float4*>(H + (size_t)s * 128 + lane * 4);
        acc.x = fmaf(w, v.x, acc.x); acc.y = fmaf(w, v.y, acc.y);
        acc.z = fmaf(w, v.z, acc.z); acc.w = fmaf(w, v.w, acc.w);
    }
    // self loop
    {
        const float2 asv = AS[i];
        float a = (hs ? asv.y : asv.x) + ad;
        a = a > 0.f ? a : NEG_SLOPE * a;
        const float w = __expf(a);
        den += w;
        const float4 v = *reinterpret_cast<const float4*>(H + (size_t)i * 128 + lane * 4);
        acc.x = fmaf(w, v.x, acc.x); acc.y = fmaf(w, v.y, acc.y);
        acc.z = fmaf(w, v.z, acc.z); acc.w = fmaf(w, v.w, acc.w);
    }
    const float inv = 1.0f / den;
    const float4 bv = *reinterpret_cast<const float4*>(b1 + lane * 4);
    float4 o;
    o.x = acc.x * inv + bv.x; o.y = acc.y * inv + bv.y;
    o.z = acc.z * inv + bv.z; o.w = acc.w * inv + bv.w;
    *reinterpret_cast<float4*>(OUT + (size_t)i * 128 + lane * 4) = o;
}

// ---- per-column sum / sumsq over agg1 (R3) ----
__global__ void bnstats_k(const float* __restrict__ A, float* __restrict__ colsum,
                          float* __restrict__ colsq, int n)
{
    const int c = threadIdx.x;                 // 128 threads
    const int r0 = blockIdx.x * 256;
    const int r1 = min(r0 + 256, n);
    float s = 0.f, q = 0.f;
    for (int r = r0; r < r1; r++) {
        float v = A[(size_t)r * 128 + c];
        s += v; q = fmaf(v, v, q);
    }
    atomicAdd(&colsum[c], s);
    atomicAdd(&colsq[c], q);
}

__global__ void bnfold_k(const float* __restrict__ colsum, const float* __restrict__ colsq,
                         const float* __restrict__ gamma, const float* __restrict__ beta,
                         float* __restrict__ scale, float* __restrict__ shift, int n)
{
    const int t = threadIdx.x;
    float inv_n = 1.0f / (float)n;
    float mean = colsum[t] * inv_n;
    float var  = colsq[t] * inv_n - mean * mean;
    float sc   = gamma[t] * rsqrtf(var + BN_EPS_F);
    scale[t] = sc;
    shift[t] = beta[t] - mean * sc;
}

// ---- layer-2 gather (R3) + head-mean + bias + log_softmax ----
__global__ __launch_bounds__(256)
void gather2_k(const int* __restrict__ rowptr, const int* __restrict__ col,
               const float2* __restrict__ AS, const float2* __restrict__ AD,
               const float* __restrict__ H, const float* __restrict__ b2,
               float* __restrict__ out, int n)
{
    const int lane = threadIdx.x & 31;
    const int i = (blockIdx.x * blockDim.x + threadIdx.x) >> 5;
    if (i >= n) return;
    const bool act = lane < 20;               // lane*4 < 80
    const bool hs  = lane >= 10;              // lane*4 >= 40 (head1)
    const float2 adv = AD[i];
    const float ad = hs ? adv.y : adv.x;

    float4 acc = make_float4(0.f, 0.f, 0.f, 0.f);
    float den = 0.f;
    const int beg = rowptr[i], end = rowptr[i + 1];
    #pragma unroll 4
    for (int e = beg; e < end; e++) {
        const int s = __ldg(col + e);
        const float2 asv = __ldg(AS + s);
        float a = (hs ? asv.y : asv.x) + ad;
        a = a > 0.f ? a : NEG_SLOPE * a;
        const float w = __expf(a);
        den += w;
        if (act) {
            const float4 v = *reinterpret_cast<const float4*>(H + (size_t)s * 80 + lane * 4);
            acc.x = fmaf(w, v.x, acc.x); acc.y = fmaf(w, v.y, acc.y);
            acc.z = fmaf(w, v.z, acc.z); acc.w = fmaf(w, v.w, acc.w);
        }
    }
    // self loop
    {
        const float2 asv = AS[i];
        float a = (hs ? asv.y : asv.x) + ad;
        a = a > 0.f ? a : NEG_SLOPE * a;
        const float w = __expf(a);
        den += w;
        if (act) {
            const float4 v = *reinterpret_cast<const float4*>(H + (size_t)i * 80 + lane * 4);
            acc.x = fmaf(w, v.x, acc.x); acc.y = fmaf(w, v.y, acc.y);
            acc.z = fmaf(w, v.z, acc.z); acc.w = fmaf(w, v.w, acc.w);
        }
    }
    const float inv = 1.0f / den;
    float4 v;
    v.x = acc.x * inv; v.y = acc.y * inv; v.z = acc.z * inv; v.w = acc.w * inv;

    // head mean: lanes 0..9 pair with lanes 10..19
    float4 o;
    o.x = __shfl_sync(FULLM, v.x, lane + 10);
    o.y = __shfl_sync(FULLM, v.y, lane + 10);
    o.z = __shfl_sync(FULLM, v.z, lane + 10);
    o.w = __shfl_sync(FULLM, v.w, lane + 10);

    float4 m = make_float4(-1e30f, -1e30f, -1e30f, -1e30f);
    if (lane < 10) {
        const float4 bv = *reinterpret_cast<const float4*>(b2 + lane * 4);
        m.x = 0.5f * (v.x + o.x) + bv.x;
        m.y = 0.5f * (v.y + o.y) + bv.y;
        m.z = 0.5f * (v.z + o.z) + bv.z;
        m.w = 0.5f * (v.w + o.w) + bv.w;
    }
    float mm = fmaxf(fmaxf(m.x, m.y), fmaxf(m.z, m.w));
    #pragma unroll
    for (int off = 16; off > 0; off >>= 1)
        mm = fmaxf(mm, __shfl_xor_sync(FULLM, mm, off));
    float ssum = 0.f;
    if (lane < 10)
        ssum = __expf(m.x - mm) + __expf(m.y - mm) + __expf(m.z - mm) + __expf(m.w - mm);
    #pragma unroll
    for (int off = 16; off > 0; off >>= 1)
        ssum += __shfl_xor_sync(FULLM, ssum, off);
    const float lse = mm + __logf(ssum);

    if (lane < 10) {
        float4 r;
        r.x = m.x - lse; r.y = m.y - lse; r.z = m.z - lse; r.w = m.w - lse;
        *reinterpret_cast<float4*>(out + (size_t)i * 40 + lane * 4) = r;
    }
}

// ------------------------------- launcher -------------------------------
extern "C" void kernel_launch(void* const* d_in, const int* in_sizes, int n_in,
                              void* d_out, int out_size)
{
    const float* x      = (const float*)d_in[0];
    const int*   ei     = (const int*)  d_in[1];
    const float* W1     = (const float*)d_in[2];
    const float* att_s1 = (const float*)d_in[3];
    const float* att_d1 = (const float*)d_in[4];
    const float* b1     = (const float*)d_in[5];
    const float* gamma  = (const float*)d_in[6];
    const float* beta   = (const float*)d_in[7];
    const float* W2     = (const float*)d_in[8];
    const float* att_s2 = (const float*)d_in[9];
    const float* att_d2 = (const float*)d_in[10];
    const float* b2     = (const float*)d_in[11];
    float* out = (float*)d_out;

    const int n = in_sizes[0] / 128;
    const int E = in_sizes[1] / 2;
    const int* src = ei;
    const int* dst = ei + E;

    float *h1, *agg1, *h2, *colsum, *colsq, *scale, *shift;
    float2 *as1, *ad1, *as2, *ad2;
    int *deg, *incl, *rowptr, *cursor, *colarr, *bsum;
    cudaGetSymbolAddress((void**)&h1,     g_h1);
    cudaGetSymbolAddress((void**)&agg1,   g_agg1);
    cudaGetSymbolAddress((void**)&h2,     g_h2);
    cudaGetSymbolAddress((void**)&as1,    g_as1);
    cudaGetSymbolAddress((void**)&ad1,    g_ad1);
    cudaGetSymbolAddress((void**)&as2,    g_as2);
    cudaGetSymbolAddress((void**)&ad2,    g_ad2);
    cudaGetSymbolAddress((void**)&deg,    g_deg);
    cudaGetSymbolAddress((void**)&incl,   g_incl);
    cudaGetSymbolAddress((void**)&rowptr, g_rowptr);
    cudaGetSymbolAddress((void**)&cursor, g_cursor);
    cudaGetSymbolAddress((void**)&colarr, g_col);
    cudaGetSymbolAddress((void**)&bsum,   g_bsum);
    cudaGetSymbolAddress((void**)&colsum, g_colsum);
    cudaGetSymbolAddress((void**)&colsq,  g_colsq);
    cudaGetSymbolAddress((void**)&scale,  g_scale);
    cudaGetSymbolAddress((void**)&shift,  g_shift);

    const size_t smem1 = (128 * 128 + 64 * 132) * sizeof(float);  // 99328 B
    const size_t smem2 = (128 * 80  + 64 * 132) * sizeof(float);  // 74752 B
    cudaFuncSetAttribute((const void*)gemm_k<128>, cudaFuncAttributeMaxDynamicSharedMemorySize, (int)smem1);
    cudaFuncSetAttribute((const void*)gemm_k<80>,  cudaFuncAttributeMaxDynamicSharedMemorySize, (int)smem2);

    const int gb = (n + 63) / 64;         // gemm blocks
    const int wb = (n * 32 + 255) / 256;  // warp-per-node blocks
    const int nb = (n + 1023) / 1024;     // scan blocks

    // ---- CSR build (shared by both layers) ----
    zero_init_k<<<(n + 255) / 256, 256>>>(deg, colsum, colsq, n);
    hist_k<<<(E + 255) / 256, 256>>>(dst, deg, E);
    scan1_k<<<nb, 1024>>>(deg, incl, bsum, n);
    scan2_k<<<1, 128>>>(bsum, nb);
    scan3_k<<<(n + 255) / 256, 256>>>(incl, bsum, deg, rowptr, cursor, n);
    fill_k<<<(E + 255) / 256, 256>>>(src, dst, cursor, colarr, E);

    // ---- layer 1 ----
    gemm_k<128><<<gb, 256, smem1>>>(x, W1, h1, n, nullptr, nullptr,
                                    att_s1, att_d1, as1, ad1);
    gather1_k<<<wb, 256>>>(rowptr, colarr, as1, ad1, h1, b1, agg1, n);

    // ---- batchnorm stats + fold ----
    bnstats_k<<<(n + 255) / 256, 128>>>(agg1, colsum, colsq, n);
    bnfold_k<<<1, 128>>>(colsum, colsq, gamma, beta, scale, shift, n);

    // ---- layer 2 (BN folded into GEMM A-load) ----
    gemm_k<80><<<gb, 256, smem2>>>(agg1, W2, h2, n, scale, shift,
                                   att_s2, att_d2, as2, ad2);
    gather2_k<<<wb, 256>>>(rowptr, colarr, as2, ad2, h2, b2, out, n);
}

// round 9
// speedup vs baseline: 1.2906x; 1.0551x over previous
#include <cuda_runtime.h>
#include <cuda_fp16.h>

#define NEG_SLOPE 0.2f
#define BN_EPS_F  1e-5f
#define FULLM 0xffffffffu

static constexpr int NMAX = 100000;
static constexpr int EMAX = 1700000;

// ---------------- scratch (static device globals; no allocation) ----------------
__device__ __half g_h1  [(size_t)NMAX * 128];   // fp16 activations (gather input only)
__device__ float  g_agg1[(size_t)NMAX * 128];   // fp32 (BN + GEMM2 input)
__device__ __half g_h2  [(size_t)NMAX * 80];
__device__ float2 g_as1 [NMAX];
__device__ float2 g_ad1 [NMAX];
__device__ float2 g_as2 [NMAX];
__device__ float2 g_ad2 [NMAX];
__device__ int    g_deg   [NMAX];
__device__ int    g_incl  [NMAX];
__device__ int    g_rowptr[NMAX + 1];
__device__ int    g_cursor[NMAX];
__device__ int    g_col   [EMAX];
__device__ int    g_bsum  [256];
__device__ float  g_colsum[128];
__device__ float  g_colsq [128];
__device__ float  g_scale [128];
__device__ float  g_shift [128];

// ---------------- packed f32x2 helpers (sm_103a FFMA2 path) ----------------
__device__ __forceinline__ unsigned long long pack2(float lo, float hi) {
    unsigned long long r;
    asm("mov.b64 %0, {%1, %2};" : "=l"(r) : "f"(lo), "f"(hi));
    return r;
}
__device__ __forceinline__ void fma2(unsigned long long& d, unsigned long long a,
                                     unsigned long long b) {
    asm("fma.rn.f32x2 %0, %1, %2, %0;" : "+l"(d) : "l"(a), "l"(b));
}
__device__ __forceinline__ void unpack2(unsigned long long v, float& lo, float& hi) {
    asm("mov.b64 {%0, %1}, %2;" : "=f"(lo), "=f"(hi) : "l"(v));
}

// ---------------- CSR build ----------------
__global__ void zero_init_k(int* deg, float* colsum, float* colsq, int n) {
    int i = blockIdx.x * blockDim.x + threadIdx.x;
    if (i < n) deg[i] = 0;
    if (i < 128) { colsum[i] = 0.f; colsq[i] = 0.f; }
}

__global__ void hist_k(const int* __restrict__ dst, int* __restrict__ deg, int E) {
    int e = blockIdx.x * blockDim.x + threadIdx.x;
    if (e < E) atomicAdd(&deg[dst[e]], 1);
}

// per-block (1024) inclusive scan + block sums
__global__ void scan1_k(const int* __restrict__ deg, int* __restrict__ incl,
                        int* __restrict__ bsum, int n) {
    __shared__ int wsum[32];
    const int tid = threadIdx.x;
    const int gid = blockIdx.x * 1024 + tid;
    const int lane = tid & 31, w = tid >> 5;
    int x = (gid < n) ? deg[gid] : 0;
    #pragma unroll
    for (int o = 1; o < 32; o <<= 1) {
        int t = __shfl_up_sync(FULLM, x, o);
        if (lane >= o) x += t;
    }
    if (lane == 31) wsum[w] = x;
    __syncthreads();
    if (w == 0) {
        int y = wsum[lane];
        #pragma unroll
        for (int o = 1; o < 32; o <<= 1) {
            int t = __shfl_up_sync(FULLM, y, o);
            if (lane >= o) y += t;
        }
        wsum[lane] = y;
    }
    __syncthreads();
    if (w > 0) x += wsum[w - 1];
    if (gid < n) incl[gid] = x;
    if (tid == 1023) bsum[blockIdx.x] = x;
}

// parallel exclusive scan of <=128 block sums
__global__ void scan2_k(int* bsum, int nb) {
    __shared__ int ws[4];
    const int tid = threadIdx.x, lane = tid & 31, w = tid >> 5;
    int orig = (tid < nb) ? bsum[tid] : 0;
    int x = orig;
    #pragma unroll
    for (int o = 1; o < 32; o <<= 1) {
        int t = __shfl_up_sync(FULLM, x, o);
        if (lane >= o) x += t;
    }
    if (lane == 31) ws[w] = x;
    __syncthreads();
    int add = 0;
    #pragma unroll
    for (int k = 0; k < 4; k++) if (k < w) add += ws[k];
    if (tid < nb) bsum[tid] = x + add - orig;   // exclusive
}

__global__ void scan3_k(const int* __restrict__ incl, const int* __restrict__ bsum,
                        const int* __restrict__ deg, int* __restrict__ rowptr,
                        int* __restrict__ cursor, int n) {
    int i = blockIdx.x * blockDim.x + threadIdx.x;
    if (i < n) {
        int v = incl[i] + bsum[i >> 10];
        rowptr[i + 1] = v;
        cursor[i] = v - deg[i];
    }
    if (i == 0) rowptr[0] = 0;
}

__global__ void fill_k(const int* __restrict__ src, const int* __restrict__ dst,
                       int* __restrict__ cursor, int* __restrict__ col, int E) {
    int e = blockIdx.x * blockDim.x + threadIdx.x;
    if (e < E) {
        int p = atomicAdd(&cursor[dst[e]], 1);
        col[p] = src[e];
    }
}

// ---- GEMM: H[n,NOUT](fp16) = X[n,128] @ W[128,NOUT] via packed f32x2 FMA.
//      Optional BN fold on X load; fused AS/AD attention epilogue (fp32 exact). ----
template<int NOUT>
__global__ __launch_bounds__(256, 2)
void gemm_k(const float* __restrict__ X, const float* __restrict__ W,
            __half* __restrict__ H, int n,
            const float* __restrict__ scale, const float* __restrict__ shift,
            const float* __restrict__ attS, const float* __restrict__ attD,
            float2* __restrict__ AS, float2* __restrict__ AD)
{
    constexpr int TN = (NOUT == 128) ? 8 : 5;
    constexpr int NP = TN / 2;
    constexpr bool ODD = (TN & 1) != 0;
    constexpr int HALF = NOUT / 2;

    extern __shared__ float smem[];
    float* sW = smem;                           // [128 * NOUT]
    float* sX = smem + 128 * NOUT;              // [64 * 132]

    const int tid = threadIdx.x;
    const int tx  = tid & 15;
    const int ty  = tid >> 4;
    const int row0 = blockIdx.x * 64;

    for (int i = tid; i < 128 * NOUT; i += 256) sW[i] = W[i];
    const bool bn = (scale != nullptr);
    for (int i = tid; i < 64 * 128; i += 256) {
        int r = i >> 7, c = i & 127;
        int gr = row0 + r;
        float v = (gr < n) ? X[(size_t)gr * 128 + c] : 0.0f;
        if (bn) v = fmaf(v, scale[c], shift[c]);
        sX[r * 132 + c] = v;
    }
    __syncthreads();

    unsigned long long acc2[4][NP];
    float acco[4];
    #pragma unroll
    for (int i = 0; i < 4; i++) {
        #pragma unroll
        for (int p = 0; p < NP; p++) acc2[i][p] = 0ull;
        acco[i] = 0.f;
    }

    #pragma unroll 8
    for (int k = 0; k < 128; k++) {
        float a[4];
        unsigned long long a2[4];
        #pragma unroll
        for (int i = 0; i < 4; i++) {
            a[i] = sX[(ty * 4 + i) * 132 + k];
            a2[i] = pack2(a[i], a[i]);
        }
        unsigned long long bp[NP];
        float bo = 0.f;
        if constexpr (NOUT == 128) {
            const float4* q = reinterpret_cast<const float4*>(sW + k * 128 + tx * 8);
            float4 b0 = q[0], b1 = q[1];
            bp[0] = pack2(b0.x, b0.y); bp[1] = pack2(b0.z, b0.w);
            bp[2] = pack2(b1.x, b1.y); bp[3] = pack2(b1.z, b1.w);
        } else {
            float4 b0 = *reinterpret_cast<const float4*>(sW + k * 80 + tx * 4);
            bp[0] = pack2(b0.x, b0.y); bp[1] = pack2(b0.z, b0.w);
            bo = sW[k * 80 + 64 + tx];
        }
        #pragma unroll
        for (int i = 0; i < 4; i++) {
            #pragma unroll
            for (int p = 0; p < NP; p++) fma2(acc2[i][p], a2[i], bp[p]);
            if constexpr (ODD) acco[i] = fmaf(a[i], bo, acco[i]);
        }
    }

    float acc[4][TN];
    #pragma unroll
    for (int i = 0; i < 4; i++) {
        #pragma unroll
        for (int p = 0; p < NP; p++) unpack2(acc2[i][p], acc[i][2 * p], acc[i][2 * p + 1]);
        if constexpr (ODD) acc[i][TN - 1] = acco[i];
    }

    int cmap[TN];
    #pragma unroll
    for (int j = 0; j < TN; j++) {
        if constexpr (NOUT == 128) cmap[j] = tx * 8 + j;
        else cmap[j] = (j < 4) ? (tx * 4 + j) : (64 + tx);
    }

    // store H as fp16 (vectorized)
    #pragma unroll
    for (int i = 0; i < 4; i++) {
        int gr = row0 + ty * 4 + i;
        if (gr < n) {
            if constexpr (NOUT == 128) {
                __half2 h0 = __floats2half2_rn(acc[i][0], acc[i][1]);
                __half2 h1v = __floats2half2_rn(acc[i][2], acc[i][3]);
                __half2 h2v = __floats2half2_rn(acc[i][4], acc[i][5]);
                __half2 h3 = __floats2half2_rn(acc[i][6], acc[i][7]);
                uint4 pkt;
                pkt.x = *reinterpret_cast<unsigned int*>(&h0);
                pkt.y = *reinterpret_cast<unsigned int*>(&h1v);
                pkt.z = *reinterpret_cast<unsigned int*>(&h2v);
                pkt.w = *reinterpret_cast<unsigned int*>(&h3);
                *reinterpret_cast<uint4*>(H + (size_t)gr * 128 + tx * 8) = pkt;
            } else {
                __half2 h0 = __floats2half2_rn(acc[i][0], acc[i][1]);
                __half2 h1v = __floats2half2_rn(acc[i][2], acc[i][3]);
                uint2 pkt;
                pkt.x = *reinterpret_cast<unsigned int*>(&h0);
                pkt.y = *reinterpret_cast<unsigned int*>(&h1v);
                *reinterpret_cast<uint2*>(H + (size_t)gr * 80 + tx * 4) = pkt;
                H[(size_t)gr * 80 + 64 + tx] = __float2half_rn(acc[i][4]);
            }
        }
    }

    // fused attention dot products (fp32 exact), per head, 16-lane reduce
    float av[TN], dv[TN];
    #pragma unroll
    for (int j = 0; j < TN; j++) {
        av[j] = attS[cmap[j]];
        dv[j] = attD[cmap[j]];
    }
    #pragma unroll
    for (int i = 0; i < 4; i++) {
        float ps0 = 0.f, ps1 = 0.f, pd0 = 0.f, pd1 = 0.f;
        #pragma unroll
        for (int j = 0; j < TN; j++) {
            if (cmap[j] < HALF) {
                ps0 = fmaf(acc[i][j], av[j], ps0);
                pd0 = fmaf(acc[i][j], dv[j], pd0);
            } else {
                ps1 = fmaf(acc[i][j], av[j], ps1);
                pd1 = fmaf(acc[i][j], dv[j], pd1);
            }
        }
        #pragma unroll
        for (int o = 1; o < 16; o <<= 1) {
            ps0 += __shfl_xor_sync(FULLM, ps0, o);
            ps1 += __shfl_xor_sync(FULLM, ps1, o);
            pd0 += __shfl_xor_sync(FULLM, pd0, o);
            pd1 += __shfl_xor_sync(FULLM, pd1, o);
        }
        int gr = row0 + ty * 4 + i;
        if (tx == 0 && gr < n) {
            AS[gr] = make_float2(ps0, ps1);
            AD[gr] = make_float2(pd0, pd1);
        }
    }
}

// ---- layer-1 gather: warp per dst node; fp16 rows, fp32 accumulate ----
__global__ __launch_bounds__(256)
void gather1_k(const int* __restrict__ rowptr, const int* __restrict__ col,
               const float2* __restrict__ AS, const float2* __restrict__ AD,
               const __half* __restrict__ H, const float* __restrict__ b1,
               float* __restrict__ OUT, int n)
{
    const int lane = threadIdx.x & 31;
    const int i = (blockIdx.x * blockDim.x + threadIdx.x) >> 5;
    if (i >= n) return;
    const bool hs = lane >= 16;               // head1 for cols >= 64
    const float2 adv = AD[i];
    const float ad = hs ? adv.y : adv.x;

    float4 acc = make_float4(0.f, 0.f, 0.f, 0.f);
    float den = 0.f;
    const int beg = rowptr[i], end = rowptr[i + 1];
    #pragma unroll 4
    for (int e = beg; e < end; e++) {
        const int s = __ldg(col + e);
        const float2 asv = __ldg(AS + s);
        float a = (hs ? asv.y : asv.x) + ad;
        a = a > 0.f ? a : NEG_SLOPE * a;
        const float w = __expf(a);
        den += w;
        const uint2 raw = *reinterpret_cast<const uint2*>(H + (size_t)s * 128 + lane * 4);
        const float2 f01 = __half22float2(*reinterpret_cast<const __half2*>(&raw.x));
        const float2 f23 = __half22float2(*reinterpret_cast<const __half2*>(&raw.y));
        acc.x = fmaf(w, f01.x, acc.x); acc.y = fmaf(w, f01.y, acc.y);
        acc.z = fmaf(w, f23.x, acc.z); acc.w = fmaf(w, f23.y, acc.w);
    }
    // self loop
    {
        const float2 asv = AS[i];
        float a = (hs ? asv.y : asv.x) + ad;
        a = a > 0.f ? a : NEG_SLOPE * a;
        const float w = __expf(a);
        den += w;
        const uint2 raw = *reinterpret_cast<const uint2*>(H + (size_t)i * 128 + lane * 4);
        const float2 f01 = __half22float2(*reinterpret_cast<const __half2*>(&raw.x));
        const float2 f23 = __half22float2(*reinterpret_cast<const __half2*>(&raw.y));
        acc.x = fmaf(w, f01.x, acc.x); acc.y = fmaf(w, f01.y, acc.y);
        acc.z = fmaf(w, f23.x, acc.z); acc.w = fmaf(w, f23.y, acc.w);
    }
    const float inv = 1.0f / den;
    const float4 bv = *reinterpret_cast<const float4*>(b1 + lane * 4);
    float4 o;
    o.x = acc.x * inv + bv.x; o.y = acc.y * inv + bv.y;
    o.z = acc.z * inv + bv.z; o.w = acc.w * inv + bv.w;
    *reinterpret_cast<float4*>(OUT + (size_t)i * 128 + lane * 4) = o;
}

// ---- per-column sum / sumsq over agg1 ----
__global__ void bnstats_k(const float* __restrict__ A, float* __restrict__ colsum,
                          float* __restrict__ colsq, int n)
{
    const int c = threadIdx.x;                 // 128 threads
    const int r0 = blockIdx.x * 256;
    const int r1 = min(r0 + 256, n);
    float s = 0.f, q = 0.f;
    for (int r = r0; r < r1; r++) {
        float v = A[(size_t)r * 128 + c];
        s += v; q = fmaf(v, v, q);
    }
    atomicAdd(&colsum[c], s);
    atomicAdd(&colsq[c], q);
}

__global__ void bnfold_k(const float* __restrict__ colsum, const float* __restrict__ colsq,
                         const float* __restrict__ gamma, const float* __restrict__ beta,
                         float* __restrict__ scale, float* __restrict__ shift, int n)
{
    const int t = threadIdx.x;
    float inv_n = 1.0f / (float)n;
    float mean = colsum[t] * inv_n;
    float var  = colsq[t] * inv_n - mean * mean;
    float sc   = gamma[t] * rsqrtf(var + BN_EPS_F);
    scale[t] = sc;
    shift[t] = beta[t] - mean * sc;
}

// ---- layer-2 gather (fp16 rows) + head-mean + bias + log_softmax ----
__global__ __launch_bounds__(256)
void gather2_k(const int* __restrict__ rowptr, const int* __restrict__ col,
               const float2* __restrict__ AS, const float2* __restrict__ AD,
               const __half* __restrict__ H, const float* __restrict__ b2,
               float* __restrict__ out, int n)
{
    const int lane = threadIdx.x & 31;
    const int i = (blockIdx.x * blockDim.x + threadIdx.x) >> 5;
    if (i >= n) return;
    const bool act = lane < 20;               // lane*4 < 80
    const bool hs  = lane >= 10;              // head1 for cols >= 40
    const float2 adv = AD[i];
    const float ad = hs ? adv.y : adv.x;

    float4 acc = make_float4(0.f, 0.f, 0.f, 0.f);
    float den = 0.f;
    const int beg = rowptr[i], end = rowptr[i + 1];
    #pragma unroll 4
    for (int e = beg; e < end; e++) {
        const int s = __ldg(col + e);
        const float2 asv = __ldg(AS + s);
        float a = (hs ? asv.y : asv.x) + ad;
        a = a > 0.f ? a : NEG_SLOPE * a;
        const float w = __expf(a);
        den += w;
        if (act) {
            const uint2 raw = *reinterpret_cast<const uint2*>(H + (size_t)s * 80 + lane * 4);
            const float2 f01 = __half22float2(*reinterpret_cast<const __half2*>(&raw.x));
            const float2 f23 = __half22float2(*reinterpret_cast<const __half2*>(&raw.y));
            acc.x = fmaf(w, f01.x, acc.x); acc.y = fmaf(w, f01.y, acc.y);
            acc.z = fmaf(w, f23.x, acc.z); acc.w = fmaf(w, f23.y, acc.w);
        }
    }
    // self loop
    {
        const float2 asv = AS[i];
        float a = (hs ? asv.y : asv.x) + ad;
        a = a > 0.f ? a : NEG_SLOPE * a;
        const float w = __expf(a);
        den += w;
        if (act) {
            const uint2 raw = *reinterpret_cast<const uint2*>(H + (size_t)i * 80 + lane * 4);
            const float2 f01 = __half22float2(*reinterpret_cast<const __half2*>(&raw.x));
            const float2 f23 = __half22float2(*reinterpret_cast<const __half2*>(&raw.y));
            acc.x = fmaf(w, f01.x, acc.x); acc.y = fmaf(w, f01.y, acc.y);
            acc.z = fmaf(w, f23.x, acc.z); acc.w = fmaf(w, f23.y, acc.w);
        }
    }
    const float inv = 1.0f / den;
    float4 v;
    v.x = acc.x * inv; v.y = acc.y * inv; v.z = acc.z * inv; v.w = acc.w * inv;

    // head mean: lanes 0..9 pair with lanes 10..19
    float4 o;
    o.x = __shfl_sync(FULLM, v.x, lane + 10);
    o.y = __shfl_sync(FULLM, v.y, lane + 10);
    o.z = __shfl_sync(FULLM, v.z, lane + 10);
    o.w = __shfl_sync(FULLM, v.w, lane + 10);

    float4 m = make_float4(-1e30f, -1e30f, -1e30f, -1e30f);
    if (lane < 10) {
        const float4 bv = *reinterpret_cast<const float4*>(b2 + lane * 4);
        m.x = 0.5f * (v.x + o.x) + bv.x;
        m.y = 0.5f * (v.y + o.y) + bv.y;
        m.z = 0.5f * (v.z + o.z) + bv.z;
        m.w = 0.5f * (v.w + o.w) + bv.w;
    }
    float mm = fmaxf(fmaxf(m.x, m.y), fmaxf(m.z, m.w));
    #pragma unroll
    for (int off = 16; off > 0; off >>= 1)
        mm = fmaxf(mm, __shfl_xor_sync(FULLM, mm, off));
    float ssum = 0.f;
    if (lane < 10)
        ssum = __expf(m.x - mm) + __expf(m.y - mm) + __expf(m.z - mm) + __expf(m.w - mm);
    #pragma unroll
    for (int off = 16; off > 0; off >>= 1)
        ssum += __shfl_xor_sync(FULLM, ssum, off);
    const float lse = mm + __logf(ssum);

    if (lane < 10) {
        float4 r;
        r.x = m.x - lse; r.y = m.y - lse; r.z = m.z - lse; r.w = m.w - lse;
        *reinterpret_cast<float4*>(out + (size_t)i * 40 + lane * 4) = r;
    }
}

// ------------------------------- launcher -------------------------------
extern "C" void kernel_launch(void* const* d_in, const int* in_sizes, int n_in,
                              void* d_out, int out_size)
{
    const float* x      = (const float*)d_in[0];
    const int*   ei     = (const int*)  d_in[1];
    const float* W1     = (const float*)d_in[2];
    const float* att_s1 = (const float*)d_in[3];
    const float* att_d1 = (const float*)d_in[4];
    const float* b1     = (const float*)d_in[5];
    const float* gamma  = (const float*)d_in[6];
    const float* beta   = (const float*)d_in[7];
    const float* W2     = (const float*)d_in[8];
    const float* att_s2 = (const float*)d_in[9];
    const float* att_d2 = (const float*)d_in[10];
    const float* b2     = (const float*)d_in[11];
    float* out = (float*)d_out;

    const int n = in_sizes[0] / 128;
    const int E = in_sizes[1] / 2;
    const int* src = ei;
    const int* dst = ei + E;

    float *agg1, *colsum, *colsq, *scale, *shift;
    __half *h1, *h2;
    float2 *as1, *ad1, *as2, *ad2;
    int *deg, *incl, *rowptr, *cursor, *colarr, *bsum;
    cudaGetSymbolAddress((void**)&h1,     g_h1);
    cudaGetSymbolAddress((void**)&agg1,   g_agg1);
    cudaGetSymbolAddress((void**)&h2,     g_h2);
    cudaGetSymbolAddress((void**)&as1,    g_as1);
    cudaGetSymbolAddress((void**)&ad1,    g_ad1);
    cudaGetSymbolAddress((void**)&as2,    g_as2);
    cudaGetSymbolAddress((void**)&ad2,    g_ad2);
    cudaGetSymbolAddress((void**)&deg,    g_deg);
    cudaGetSymbolAddress((void**)&incl,   g_incl);
    cudaGetSymbolAddress((void**)&rowptr, g_rowptr);
    cudaGetSymbolAddress((void**)&cursor, g_cursor);
    cudaGetSymbolAddress((void**)&colarr, g_col);
    cudaGetSymbolAddress((void**)&bsum,   g_bsum);
    cudaGetSymbolAddress((void**)&colsum, g_colsum);
    cudaGetSymbolAddress((void**)&colsq,  g_colsq);
    cudaGetSymbolAddress((void**)&scale,  g_scale);
    cudaGetSymbolAddress((void**)&shift,  g_shift);

    const size_t smem1 = (128 * 128 + 64 * 132) * sizeof(float);  // 99328 B
    const size_t smem2 = (128 * 80  + 64 * 132) * sizeof(float);  // 74752 B
    cudaFuncSetAttribute((const void*)gemm_k<128>, cudaFuncAttributeMaxDynamicSharedMemorySize, (int)smem1);
    cudaFuncSetAttribute((const void*)gemm_k<80>,  cudaFuncAttributeMaxDynamicSharedMemorySize, (int)smem2);

    const int gb = (n + 63) / 64;         // gemm blocks
    const int wb = (n * 32 + 255) / 256;  // warp-per-node blocks
    const int nb = (n + 1023) / 1024;     // scan blocks

    // ---- CSR build (shared by both layers) ----
    zero_init_k<<<(n + 255) / 256, 256>>>(deg, colsum, colsq, n);
    hist_k<<<(E + 255) / 256, 256>>>(dst, deg, E);
    scan1_k<<<nb, 1024>>>(deg, incl, bsum, n);
    scan2_k<<<1, 128>>>(bsum, nb);
    scan3_k<<<(n + 255) / 256, 256>>>(incl, bsum, deg, rowptr, cursor, n);
    fill_k<<<(E + 255) / 256, 256>>>(src, dst, cursor, colarr, E);

    // ---- layer 1 ----
    gemm_k<128><<<gb, 256, smem1>>>(x, W1, h1, n, nullptr, nullptr,
                                    att_s1, att_d1, as1, ad1);
    gather1_k<<<wb, 256>>>(rowptr, colarr, as1, ad1, h1, b1, agg1, n);

    // ---- batchnorm stats + fold ----
    bnstats_k<<<(n + 255) / 256, 128>>>(agg1, colsum, colsq, n);
    bnfold_k<<<1, 128>>>(colsum, colsq, gamma, beta, scale, shift, n);

    // ---- layer 2 (BN folded into GEMM A-load) ----
    gemm_k<80><<<gb, 256, smem2>>>(agg1, W2, h2, n, scale, shift,
                                   att_s2, att_d2, as2, ad2);
    gather2_k<<<wb, 256>>>(rowptr, colarr, as2, ad2, h2, b2, out, n);
}